// round 3
// baseline (speedup 1.0000x reference)
#include <cuda_runtime.h>
#include <math.h>

#define NN 5000
#define EE 40000

// ---------------- scratch (device globals) -----------------------------------
__device__ float g_sh1[EE * 3];    // sqrt3 * (ny, nz, nx)
__device__ float g_hly[EE * 8];    // hidden activations of ly MLP
__device__ float g_het[EE * 8];    // hidden activations of et MLP
__device__ float g_m1 [EE * 32];   // stage-1 scalar message (pre C_IP)
__device__ float g_m2 [EE * 32];   // stage-1 vector radial message (pre sh, pre C_IP)
__device__ float g_lys[EE * 32];   // ly scalar message
__device__ float g_lyv[EE * 96];   // ly vector message, plane layout [i*32+u]
__device__ float g_s  [NN * 32];   // stage-1 node scalars (mean)
__device__ float g_v  [NN * 96];   // stage-1 node vectors, plane layout [i*32+u]
__device__ float g_s2 [NN * 32];   // final node scalars
__device__ float g_v2 [NN * 96];   // final node vectors, plane layout
__device__ float g_A1 [100 * 9 * 32];
__device__ float g_A2 [100 * 9 * 32];
__device__ float g_G  [NN * 2304]; // per-node precontracted ly weights
// CSR
__device__ int g_deg_s[NN], g_deg_d[NN];
__device__ int g_off_s[NN + 1], g_off_d[NN + 1];
__device__ int g_cur_s[NN], g_cur_d[NN];
__device__ int g_csr_s[EE], g_csr_d[EE];

#define FULLMASK 0xffffffffu
__device__ __forceinline__ float siluf(float x) { return x / (1.f + __expf(-x)); }

constexpr float SQRT3      = 1.7320508075688772f;
constexpr float INV_SQRT3  = 0.57735026918962576f;
constexpr float C_IP       = 0.17677669529663687f;  // 1/sqrt(32)
constexpr float C_LY       = 0.125f;                // 1/sqrt(64)
constexpr float C_ET       = 0.08838834764831843f;  // 1/sqrt(128)
constexpr float LC         = 0.17677669529663687f;  // o3.Linear norm 1/sqrt(32)
constexpr float INV_SQRT32 = 0.17677669529663687f;
constexpr float INV_SQRT13 = 0.27735009811261457f;
constexpr float CUTOFF     = 5.0f;

// ---------------- CSR build ---------------------------------------------------

__global__ void k_zcsr(int N) {
    int i = blockIdx.x * blockDim.x + threadIdx.x;
    if (i < N) { g_deg_s[i] = 0; g_deg_d[i] = 0; }
}

__global__ void k_hist(const int* __restrict__ ei, int E) {
    int e = blockIdx.x * blockDim.x + threadIdx.x;
    if (e >= E) return;
    atomicAdd(&g_deg_s[ei[e]], 1);
    atomicAdd(&g_deg_d[ei[E + e]], 1);
}

__device__ void scan_one(const int* __restrict__ deg, int* __restrict__ off,
                         int* __restrict__ cur, int N, int* sm) {
    int t = threadIdx.x;
    int base = t * 5;
    int c[5]; int tot = 0;
#pragma unroll
    for (int j = 0; j < 5; j++) {
        c[j] = (base + j < N) ? deg[base + j] : 0;
        tot += c[j];
    }
    sm[t] = tot;
    __syncthreads();
    for (int d = 1; d < 1024; d <<= 1) {
        int v = (t >= d) ? sm[t - d] : 0;
        __syncthreads();
        sm[t] += v;
        __syncthreads();
    }
    int run = sm[t] - tot;  // exclusive prefix
#pragma unroll
    for (int j = 0; j < 5; j++) {
        if (base + j < N) { off[base + j] = run; cur[base + j] = run; run += c[j]; }
    }
    if (t == 1023) off[N] = sm[1023];
    __syncthreads();
}

__global__ void k_scan(int N) {
    __shared__ int sm[1024];
    scan_one(g_deg_s, g_off_s, g_cur_s, N, sm);
    scan_one(g_deg_d, g_off_d, g_cur_d, N, sm);
}

__global__ void k_fill(const int* __restrict__ ei, int E) {
    int e = blockIdx.x * blockDim.x + threadIdx.x;
    if (e >= E) return;
    int p = atomicAdd(&g_cur_s[ei[e]], 1);
    g_csr_s[p] = e;
    int q = atomicAdd(&g_cur_d[ei[E + e]], 1);
    g_csr_d[q] = e;
}

// ---------------- per-atom-type ip contraction --------------------------------

__global__ void k_pretype(const float* __restrict__ emb,
                          const float* __restrict__ ipW1,
                          const float* __restrict__ ipb1) {
    int t = blockIdx.x;
    int w = threadIdx.x;
    float e[32];
#pragma unroll
    for (int u = 0; u < 32; u++) e[u] = emb[t * 32 + u];
    for (int k = 0; k < 8; k++) {
        float a1 = 0.f, a2 = 0.f;
#pragma unroll
        for (int u = 0; u < 32; u++) {
            a1 += e[u] * ipW1[k * 2048 +        u * 32 + w];
            a2 += e[u] * ipW1[k * 2048 + 1024 + u * 32 + w];
        }
        g_A1[t * 288 + k * 32 + w] = a1;
        g_A2[t * 288 + k * 32 + w] = a2;
    }
    float b1 = 0.f, b2 = 0.f;
#pragma unroll
    for (int u = 0; u < 32; u++) {
        b1 += e[u] * ipb1[       u * 32 + w];
        b2 += e[u] * ipb1[1024 + u * 32 + w];
    }
    g_A1[t * 288 + 8 * 32 + w] = b1;
    g_A2[t * 288 + 8 * 32 + w] = b2;
}

// ---------------- per-edge geometry + radial MLPs + stage-1 messages ----------

__global__ void k_edge1(const float* __restrict__ coords,
                        const int*   __restrict__ atom_types,
                        const int*   __restrict__ ei,
                        const float* __restrict__ ipW0, const float* __restrict__ ipb0,
                        const float* __restrict__ lyW0, const float* __restrict__ lyb0,
                        const float* __restrict__ etW0, const float* __restrict__ etb0,
                        int E) {
    int lane = threadIdx.x & 31;
    int e = blockIdx.x * (blockDim.x >> 5) + (threadIdx.x >> 5);
    if (e >= E) return;
    int src = ei[e], dst = ei[E + e];

    float dx = coords[dst * 3 + 0] - coords[src * 3 + 0];
    float dy = coords[dst * 3 + 1] - coords[src * 3 + 1];
    float dz = coords[dst * 3 + 2] - coords[src * 3 + 2];
    float d  = sqrtf(dx * dx + dy * dy + dz * dz + 1e-12f);
    float inv_d = 1.f / d;
    float nx = dx * inv_d, ny = dy * inv_d, nz = dz * inv_d;
    float sh_0 = SQRT3 * ny, sh_1 = SQRT3 * nz, sh_2 = SQRT3 * nx;

    float attr[8];
    constexpr float STEP = CUTOFF / 9.0f;
    constexpr float INV_STEP = 9.0f / CUTOFF;
#pragma unroll
    for (int i = 0; i < 8; i++) {
        float diff = (d - (float)(i + 1) * STEP) * INV_STEP;
        attr[i] = __expf(-diff * diff) * (1.0f / 1.12f);
    }

    int grp = lane >> 3;
    int j   = lane & 7;
    const float* W0 = (grp == 1) ? lyW0 : (grp == 2) ? etW0 : ipW0;
    const float* b0 = (grp == 1) ? lyb0 : (grp == 2) ? etb0 : ipb0;
    float pre = b0[j];
#pragma unroll
    for (int i = 0; i < 8; i++) pre += attr[i] * W0[i * 8 + j];
    float myh = siluf(pre);

    if (grp == 1) g_hly[e * 8 + j] = myh;
    if (grp == 2) g_het[e * 8 + j] = myh;
    if (lane < 3) g_sh1[e * 3 + lane] = (lane == 0) ? sh_0 : (lane == 1) ? sh_1 : sh_2;

    int t = atom_types[src];
    const float* A1 = &g_A1[t * 288];
    const float* A2 = &g_A2[t * 288];
    float m1 = A1[8 * 32 + lane];
    float m2 = A2[8 * 32 + lane];
#pragma unroll
    for (int k = 0; k < 8; k++) {
        float hk = __shfl_sync(FULLMASK, myh, k);
        m1 += hk * A1[k * 32 + lane];
        m2 += hk * A2[k * 32 + lane];
    }
    g_m1[e * 32 + lane] = m1;
    g_m2[e * 32 + lane] = m2;
}

// ---------------- gather stage-1 messages by dst ------------------------------

__global__ void k_gather1(int N) {
    int lane = threadIdx.x & 31;
    int n = blockIdx.x * (blockDim.x >> 5) + (threadIdx.x >> 5);
    if (n >= N) return;
    int beg = g_off_d[n], end = g_off_d[n + 1];
    float s = 0.f, v0 = 0.f, v1 = 0.f, v2 = 0.f;
    for (int p = beg; p < end; p++) {
        int e = g_csr_d[p];
        float m1 = g_m1[e * 32 + lane];
        float m2 = g_m2[e * 32 + lane];
        float sh_0 = g_sh1[e * 3 + 0], sh_1 = g_sh1[e * 3 + 1], sh_2 = g_sh1[e * 3 + 2];
        s  += m1;
        v0 += m2 * sh_0;
        v1 += m2 * sh_1;
        v2 += m2 * sh_2;
    }
    int deg = end - beg;
    float inv = C_IP / (float)max(deg, 1);
    g_s[n * 32 + lane]       = s  * inv;
    g_v[n * 96 +      lane]  = v0 * inv;
    g_v[n * 96 + 32 + lane]  = v1 * inv;
    g_v[n * 96 + 64 + lane]  = v2 * inv;
}

// ---------------- per-node precontraction of ly weights -----------------------
// G[n][k=0..8][2 float4 rows][32 w]: {Y0,Y1,Z2_0,Z2_1} {Z2_2,Z3_0,Z3_1,Z3_2}
__global__ void __launch_bounds__(256)
k_pre_ly(const float* __restrict__ W1, const float* __restrict__ B1, int N) {
    __shared__ float s_sm[32][32];
    __shared__ float v_sm[32][96];   // plane layout [i*32+u]
    int tid = threadIdx.x;
    int w = tid & 31;
    int q = tid >> 5;
    int nb = blockIdx.x * 32;

    for (int i = tid; i < 32 * 32; i += 256) {
        int n = nb + (i >> 5);
        s_sm[i >> 5][i & 31] = (n < N) ? g_s[n * 32 + (i & 31)] : 0.f;
    }
    for (int i = tid; i < 32 * 96; i += 256) {
        int n = nb + (i / 96);
        v_sm[i / 96][i % 96] = (n < N) ? g_v[n * 96 + (i % 96)] : 0.f;
    }
    __syncthreads();

    int n0 = q * 4;

    for (int k = 0; k < 9; k++) {
        const float* Wk = (k < 8) ? (W1 + k * 4096) : B1;
        float y0[4] = {0.f, 0.f, 0.f, 0.f};
        float y1[4] = {0.f, 0.f, 0.f, 0.f};
        float z2[4][3] = {};
        float z3[4][3] = {};
#pragma unroll 4
        for (int u = 0; u < 32; u++) {
            float w0 = Wk[           u * 32 + w];
            float w1 = Wk[1024 +     u * 32 + w];
            float w2 = Wk[2048 +     u * 32 + w];
            float w3 = Wk[3072 +     u * 32 + w];
#pragma unroll
            for (int nn = 0; nn < 4; nn++) {
                float su = s_sm[n0 + nn][u];
                float v0 = v_sm[n0 + nn][     u];
                float v1 = v_sm[n0 + nn][32 + u];
                float v2 = v_sm[n0 + nn][64 + u];
                y0[nn] += su * w0;
                y1[nn] += su * w1;
                z2[nn][0] += v0 * w2;  z2[nn][1] += v1 * w2;  z2[nn][2] += v2 * w2;
                z3[nn][0] += v0 * w3;  z3[nn][1] += v1 * w3;  z3[nn][2] += v2 * w3;
            }
        }
#pragma unroll
        for (int nn = 0; nn < 4; nn++) {
            int n = nb + n0 + nn;
            if (n < N) {
                float4* Gp = reinterpret_cast<float4*>(&g_G[n * 2304]);
                Gp[(2 * k + 0) * 32 + w] = make_float4(y0[nn], y1[nn], z2[nn][0], z2[nn][1]);
                Gp[(2 * k + 1) * 32 + w] = make_float4(z2[nn][2], z3[nn][0], z3[nn][1], z3[nn][2]);
            }
        }
    }
}

// ---------------- apply ly weights: warp per src node, G in registers ---------
__global__ void __launch_bounds__(128)
k_apply_ly(int N) {
    int lane = threadIdx.x & 31;
    int n = blockIdx.x * 4 + (threadIdx.x >> 5);
    if (n >= N) return;
    int beg = g_off_s[n], end = g_off_s[n + 1];
    if (beg == end) return;

    const float4* Gp = reinterpret_cast<const float4*>(&g_G[n * 2304]);
    float4 Ga[9], Gb[9];
#pragma unroll
    for (int k = 0; k < 9; k++) {
        Ga[k] = Gp[(2 * k + 0) * 32 + lane];
        Gb[k] = Gp[(2 * k + 1) * 32 + lane];
    }

    for (int p = beg; p < end; p++) {
        int e = g_csr_s[p];
        float sh_0 = g_sh1[e * 3 + 0], sh_1 = g_sh1[e * 3 + 1], sh_2 = g_sh1[e * 3 + 2];
        const float4* hp = reinterpret_cast<const float4*>(&g_hly[e * 8]);
        float4 ha = hp[0], hb = hp[1];
        float h[9] = {ha.x, ha.y, ha.z, ha.w, hb.x, hb.y, hb.z, hb.w, 1.0f};

        float ys = 0.f, yv = 0.f;
        float z20 = 0.f, z21 = 0.f, z22 = 0.f;
        float z30 = 0.f, z31 = 0.f, z32 = 0.f;
#pragma unroll
        for (int k = 0; k < 9; k++) {
            float hk = h[k];
            ys  += hk * Ga[k].x;  yv  += hk * Ga[k].y;
            z20 += hk * Ga[k].z;  z21 += hk * Ga[k].w;
            z22 += hk * Gb[k].x;
            z30 += hk * Gb[k].y;  z31 += hk * Gb[k].z;  z32 += hk * Gb[k].w;
        }
        float out_s = ys + INV_SQRT3 * (sh_0 * z30 + sh_1 * z31 + sh_2 * z32);
        g_lys[e * 32 + lane]      = C_LY * out_s;
        g_lyv[e * 96 +      lane] = C_LY * (sh_0 * yv + z20);
        g_lyv[e * 96 + 32 + lane] = C_LY * (sh_1 * yv + z21);
        g_lyv[e * 96 + 64 + lane] = C_LY * (sh_2 * yv + z22);
    }
}

// ---------------- gather ly messages by dst + linear self-interaction ---------
__global__ void k_gather2(const float* __restrict__ Ws, const float* __restrict__ Wv, int N) {
    int lane = threadIdx.x & 31;
    int n = blockIdx.x * (blockDim.x >> 5) + (threadIdx.x >> 5);
    if (n >= N) return;
    int beg = g_off_d[n], end = g_off_d[n + 1];
    float cs = 0.f, cv0 = 0.f, cv1 = 0.f, cv2 = 0.f;
    for (int p = beg; p < end; p++) {
        int e = g_csr_d[p];
        cs  += g_lys[e * 32 + lane];
        cv0 += g_lyv[e * 96 +      lane];
        cv1 += g_lyv[e * 96 + 32 + lane];
        cv2 += g_lyv[e * 96 + 64 + lane];
    }
    int deg = end - beg;
    float inv = 1.f / (float)max(deg, 1);

    float sl  = g_s[n * 32 + lane];
    float vl0 = g_v[n * 96 +      lane];
    float vl1 = g_v[n * 96 + 32 + lane];
    float vl2 = g_v[n * 96 + 64 + lane];
    float ls = 0.f, lv0 = 0.f, lv1 = 0.f, lv2 = 0.f;
#pragma unroll 4
    for (int u = 0; u < 32; u++) {
        float su  = __shfl_sync(FULLMASK, sl,  u);
        float vu0 = __shfl_sync(FULLMASK, vl0, u);
        float vu1 = __shfl_sync(FULLMASK, vl1, u);
        float vu2 = __shfl_sync(FULLMASK, vl2, u);
        float ws = Ws[u * 32 + lane];
        float wv = Wv[u * 32 + lane];
        ls  += su  * ws;
        lv0 += vu0 * wv;
        lv1 += vu1 * wv;
        lv2 += vu2 * wv;
    }
    g_s2[n * 32 + lane]      = cs  * inv + LC * ls;
    g_v2[n * 96 +      lane] = cv0 * inv + LC * lv0;
    g_v2[n * 96 + 32 + lane] = cv1 * inv + LC * lv1;
    g_v2[n * 96 + 64 + lane] = cv2 * inv + LC * lv2;
}

// ---------------- edge output tensor product ----------------------------------
__global__ void k_et(const float* __restrict__ W1, const float* __restrict__ B1,
                     const int* __restrict__ ei, float* __restrict__ out, int E) {
    __shared__ float sW[8 * 640];
    __shared__ float sB[640];
    for (int i = threadIdx.x; i < 8 * 640; i += blockDim.x) sW[i] = W1[i];
    for (int i = threadIdx.x; i < 640;     i += blockDim.x) sB[i] = B1[i];
    __syncthreads();

    int lane = threadIdx.x & 31;   // = u
    int e = blockIdx.x * (blockDim.x >> 5) + (threadIdx.x >> 5);
    if (e >= E) return;
    int src = ei[e], dst = ei[E + e];
    float sh_0 = g_sh1[e * 3 + 0], sh_1 = g_sh1[e * 3 + 1], sh_2 = g_sh1[e * 3 + 2];
    const float4* hp = reinterpret_cast<const float4*>(&g_het[e * 8]);
    float4 ha = hp[0], hb = hp[1];
    float h[8] = {ha.x, ha.y, ha.z, ha.w, hb.x, hb.y, hb.z, hb.w};

    float x[4];
    x[0] = g_s2[src * 32 + lane];
    {
        float a = g_v2[src * 96 +      lane];
        float b = g_v2[src * 96 + 32 + lane];
        float c = g_v2[src * 96 + 64 + lane];
        x[1] = (a * sh_0 + b * sh_1 + c * sh_2) * INV_SQRT3;
    }
    x[2] = g_s2[dst * 32 + lane];
    {
        float a = g_v2[dst * 96 +      lane];
        float b = g_v2[dst * 96 + 32 + lane];
        float c = g_v2[dst * 96 + 64 + lane];
        x[3] = (a * sh_0 + b * sh_1 + c * sh_2) * INV_SQRT3;
    }

    float p0 = 0.f, p1 = 0.f, p2 = 0.f, p3 = 0.f, p4 = 0.f;
#pragma unroll
    for (int P = 0; P < 4; P++) {
        int base = P * 160 + lane * 5;
        float xp = x[P];
#pragma unroll
        for (int w = 0; w < 5; w++) {
            float wt = sB[base + w];
#pragma unroll
            for (int k = 0; k < 8; k++) wt += h[k] * sW[k * 640 + base + w];
            float contrib = xp * wt;
            if (w == 0) p0 += contrib;
            else if (w == 1) p1 += contrib;
            else if (w == 2) p2 += contrib;
            else if (w == 3) p3 += contrib;
            else p4 += contrib;
        }
    }
#pragma unroll
    for (int off = 16; off > 0; off >>= 1) {
        p0 += __shfl_xor_sync(FULLMASK, p0, off);
        p1 += __shfl_xor_sync(FULLMASK, p1, off);
        p2 += __shfl_xor_sync(FULLMASK, p2, off);
        p3 += __shfl_xor_sync(FULLMASK, p3, off);
        p4 += __shfl_xor_sync(FULLMASK, p4, off);
    }
    if (lane == 0) {
        out[e * 5 + 0] = C_ET * p0;
        out[e * 5 + 1] = C_ET * p1;
        out[e * 5 + 2] = C_ET * p2;
        out[e * 5 + 3] = C_ET * p3;
        out[e * 5 + 4] = C_ET * p4;
    }
}

// ---------------- node output MLP ---------------------------------------------
__global__ void k_nodeout(const float* __restrict__ W1, const float* __restrict__ W2,
                          float* __restrict__ out, int N) {
    int n = blockIdx.x * blockDim.x + threadIdx.x;
    if (n >= N) return;
    float s[32];
#pragma unroll
    for (int u = 0; u < 32; u++) s[u] = g_s2[n * 32 + u];
    float h[13];
#pragma unroll
    for (int j = 0; j < 13; j++) {
        float pre = 0.f;
#pragma unroll
        for (int u = 0; u < 32; u++) pre += s[u] * W1[u * 13 + j];
        pre *= INV_SQRT32;
        h[j] = siluf(pre);
    }
#pragma unroll
    for (int j2 = 0; j2 < 13; j2++) {
        float o = 0.f;
#pragma unroll
        for (int j = 0; j < 13; j++) o += h[j] * W2[j * 13 + j2];
        out[n * 13 + j2] = o * INV_SQRT13;
    }
}

// ---------------- launch ------------------------------------------------------

extern "C" void kernel_launch(void* const* d_in, const int* in_sizes, int n_in,
                              void* d_out, int out_size) {
    const float* coords     = (const float*)d_in[0];
    const int*   atom_types = (const int*)  d_in[1];
    const int*   ei         = (const int*)  d_in[2];
    const float* atom_embed = (const float*)d_in[3];
    const float* ip_W0 = (const float*)d_in[4];
    const float* ip_b0 = (const float*)d_in[5];
    const float* ip_W1 = (const float*)d_in[6];
    const float* ip_b1 = (const float*)d_in[7];
    const float* ly_W0 = (const float*)d_in[8];
    const float* ly_b0 = (const float*)d_in[9];
    const float* ly_W1 = (const float*)d_in[10];
    const float* ly_b1 = (const float*)d_in[11];
    const float* ly_Ws = (const float*)d_in[12];
    const float* ly_Wv = (const float*)d_in[13];
    const float* et_W0 = (const float*)d_in[14];
    const float* et_b0 = (const float*)d_in[15];
    const float* et_W1 = (const float*)d_in[16];
    const float* et_b1 = (const float*)d_in[17];
    const float* no_W1 = (const float*)d_in[18];
    const float* no_W2 = (const float*)d_in[19];
    float* out = (float*)d_out;

    int N = in_sizes[0] / 3;   // 5000
    int E = in_sizes[2] / 2;   // 40000

    k_zcsr<<<(N + 255) / 256, 256>>>(N);
    k_pretype<<<100, 32>>>(atom_embed, ip_W1, ip_b1);
    k_hist<<<(E + 255) / 256, 256>>>(ei, E);
    k_scan<<<1, 1024>>>(N);
    k_fill<<<(E + 255) / 256, 256>>>(ei, E);
    k_edge1<<<(E + 7) / 8, 256>>>(coords, atom_types, ei,
                                  ip_W0, ip_b0, ly_W0, ly_b0, et_W0, et_b0, E);
    k_gather1<<<(N + 7) / 8, 256>>>(N);
    k_pre_ly<<<(N + 31) / 32, 256>>>(ly_W1, ly_b1, N);
    k_apply_ly<<<(N + 3) / 4, 128>>>(N);
    k_gather2<<<(N + 7) / 8, 256>>>(ly_Ws, ly_Wv, N);
    k_et<<<(E + 7) / 8, 256>>>(et_W1, et_b1, ei, out, E);
    k_nodeout<<<(N + 127) / 128, 128>>>(no_W1, no_W2, out + (size_t)E * 5, N);
}

// round 6
// speedup vs baseline: 1.4154x; 1.4154x over previous
#include <cuda_runtime.h>
#include <math.h>

#define NN 5000
#define EE 40000

// ---------------- scratch (device globals) -----------------------------------
__device__ float g_sh1[EE * 3];    // sqrt3 * (ny, nz, nx)
__device__ float g_hly[EE * 8];    // hidden activations of ly MLP
__device__ float g_het[EE * 8];    // hidden activations of et MLP
__device__ float g_s  [NN * 32];   // stage-1 node scalars
__device__ float g_v  [NN * 96];   // stage-1 node vectors, plane layout [i*32+u]
__device__ float g_cs [NN * 32];   // layer conv scalar accum
__device__ float g_cv [NN * 96];   // layer conv vector accum, plane layout
__device__ float g_s2 [NN * 32];   // final node scalars
__device__ float g_v2 [NN * 96];   // final node vectors, plane layout
__device__ float g_cnt[NN];        // in-degree (dst)
__device__ float g_A1 [100 * 9 * 32];
__device__ float g_A2 [100 * 9 * 32];
__device__ float g_G  [NN * 2304]; // per-node precontracted ly weights
// src-CSR only
__device__ int g_deg_s[NN];
__device__ int g_off_s[NN + 1];
__device__ int g_cur_s[NN];
__device__ int g_csr_s[EE];

#define FULLMASK 0xffffffffu
__device__ __forceinline__ float siluf(float x) { return x / (1.f + __expf(-x)); }

constexpr float SQRT3      = 1.7320508075688772f;
constexpr float INV_SQRT3  = 0.57735026918962576f;
constexpr float C_IP       = 0.17677669529663687f;  // 1/sqrt(32)
constexpr float C_LY       = 0.125f;                // 1/sqrt(64)
constexpr float C_ET       = 0.08838834764831843f;  // 1/sqrt(128)
constexpr float LC         = 0.17677669529663687f;  // o3.Linear norm 1/sqrt(32)
constexpr float INV_SQRT32 = 0.17677669529663687f;
constexpr float INV_SQRT13 = 0.27735009811261457f;
constexpr float CUTOFF     = 5.0f;

// ---------------- zero + CSR build --------------------------------------------

__global__ void k_zero(int N) {
    int tid = blockIdx.x * blockDim.x + threadIdx.x;
    int stride = gridDim.x * blockDim.x;
    for (int i = tid; i < N * 32; i += stride) { g_s[i] = 0.f; g_cs[i] = 0.f; }
    for (int i = tid; i < N * 96; i += stride) { g_v[i] = 0.f; g_cv[i] = 0.f; }
    for (int i = tid; i < N;      i += stride) { g_cnt[i] = 0.f; g_deg_s[i] = 0; }
}

__global__ void k_hist_s(const int* __restrict__ ei, int E) {
    int e = blockIdx.x * blockDim.x + threadIdx.x;
    if (e < E) atomicAdd(&g_deg_s[ei[e]], 1);
}

// fast single-block scan: thread-local 5, shfl warp scan, warp-total scan
__global__ void k_scan_s(int N) {
    __shared__ int wsum[32];
    int t = threadIdx.x;          // 1024 threads
    int lane = t & 31, wid = t >> 5;
    int base = t * 5;
    int c[5]; int tot = 0;
#pragma unroll
    for (int j = 0; j < 5; j++) {
        c[j] = (base + j < N) ? g_deg_s[base + j] : 0;
        tot += c[j];
    }
    int x = tot;
#pragma unroll
    for (int d = 1; d < 32; d <<= 1) {
        int y = __shfl_up_sync(FULLMASK, x, d);
        if (lane >= d) x += y;
    }
    if (lane == 31) wsum[wid] = x;
    __syncthreads();
    if (wid == 0) {
        int w = wsum[lane];
#pragma unroll
        for (int d = 1; d < 32; d <<= 1) {
            int y = __shfl_up_sync(FULLMASK, w, d);
            if (lane >= d) w += y;
        }
        wsum[lane] = w;
    }
    __syncthreads();
    int run = ((wid > 0) ? wsum[wid - 1] : 0) + x - tot;  // exclusive prefix
#pragma unroll
    for (int j = 0; j < 5; j++) {
        if (base + j < N) { g_off_s[base + j] = run; g_cur_s[base + j] = run; run += c[j]; }
    }
    if (t == 0) g_off_s[N] = wsum[31];
}

__global__ void k_fill_s(const int* __restrict__ ei, int E) {
    int e = blockIdx.x * blockDim.x + threadIdx.x;
    if (e >= E) return;
    int p = atomicAdd(&g_cur_s[ei[e]], 1);
    g_csr_s[p] = e;
}

// ---------------- per-atom-type ip contraction --------------------------------

__global__ void k_pretype(const float* __restrict__ emb,
                          const float* __restrict__ ipW1,
                          const float* __restrict__ ipb1) {
    int t = blockIdx.x;
    int w = threadIdx.x;
    float e[32];
#pragma unroll
    for (int u = 0; u < 32; u++) e[u] = emb[t * 32 + u];
    for (int k = 0; k < 8; k++) {
        float a1 = 0.f, a2 = 0.f;
#pragma unroll
        for (int u = 0; u < 32; u++) {
            a1 += e[u] * ipW1[k * 2048 +        u * 32 + w];
            a2 += e[u] * ipW1[k * 2048 + 1024 + u * 32 + w];
        }
        g_A1[t * 288 + k * 32 + w] = a1;
        g_A2[t * 288 + k * 32 + w] = a2;
    }
    float b1 = 0.f, b2 = 0.f;
#pragma unroll
    for (int u = 0; u < 32; u++) {
        b1 += e[u] * ipb1[       u * 32 + w];
        b2 += e[u] * ipb1[1024 + u * 32 + w];
    }
    g_A1[t * 288 + 8 * 32 + w] = b1;
    g_A2[t * 288 + 8 * 32 + w] = b2;
}

// ---------------- per-edge geometry + radial MLPs + stage-1 scatter -----------

__global__ void k_edge1(const float* __restrict__ coords,
                        const int*   __restrict__ atom_types,
                        const int*   __restrict__ ei,
                        const float* __restrict__ ipW0, const float* __restrict__ ipb0,
                        const float* __restrict__ lyW0, const float* __restrict__ lyb0,
                        const float* __restrict__ etW0, const float* __restrict__ etb0,
                        int E) {
    int lane = threadIdx.x & 31;
    int e = blockIdx.x * (blockDim.x >> 5) + (threadIdx.x >> 5);
    if (e >= E) return;
    int src = ei[e], dst = ei[E + e];

    float dx = coords[dst * 3 + 0] - coords[src * 3 + 0];
    float dy = coords[dst * 3 + 1] - coords[src * 3 + 1];
    float dz = coords[dst * 3 + 2] - coords[src * 3 + 2];
    float d  = sqrtf(dx * dx + dy * dy + dz * dz + 1e-12f);
    float inv_d = 1.f / d;
    float nx = dx * inv_d, ny = dy * inv_d, nz = dz * inv_d;
    float sh_0 = SQRT3 * ny, sh_1 = SQRT3 * nz, sh_2 = SQRT3 * nx;

    float attr[8];
    constexpr float STEP = CUTOFF / 9.0f;
    constexpr float INV_STEP = 9.0f / CUTOFF;
#pragma unroll
    for (int i = 0; i < 8; i++) {
        float diff = (d - (float)(i + 1) * STEP) * INV_STEP;
        attr[i] = __expf(-diff * diff) * (1.0f / 1.12f);
    }

    int grp = lane >> 3;
    int j   = lane & 7;
    const float* W0 = (grp == 1) ? lyW0 : (grp == 2) ? etW0 : ipW0;
    const float* b0 = (grp == 1) ? lyb0 : (grp == 2) ? etb0 : ipb0;
    float pre = b0[j];
#pragma unroll
    for (int i = 0; i < 8; i++) pre += attr[i] * W0[i * 8 + j];
    float myh = siluf(pre);

    if (grp == 1) g_hly[e * 8 + j] = myh;
    if (grp == 2) g_het[e * 8 + j] = myh;
    if (lane < 3) g_sh1[e * 3 + lane] = (lane == 0) ? sh_0 : (lane == 1) ? sh_1 : sh_2;

    int t = atom_types[src];
    const float* A1 = &g_A1[t * 288];
    const float* A2 = &g_A2[t * 288];
    float m1 = A1[8 * 32 + lane];
    float m2 = A2[8 * 32 + lane];
#pragma unroll
    for (int k = 0; k < 8; k++) {
        float hk = __shfl_sync(FULLMASK, myh, k);
        m1 += hk * A1[k * 32 + lane];
        m2 += hk * A2[k * 32 + lane];
    }
    // coalesced plane-layout atomics (1 x 128B line each)
    atomicAdd(&g_s[dst * 32 + lane], C_IP * m1);
    float cm2 = C_IP * m2;
    atomicAdd(&g_v[dst * 96 +      lane], cm2 * sh_0);
    atomicAdd(&g_v[dst * 96 + 32 + lane], cm2 * sh_1);
    atomicAdd(&g_v[dst * 96 + 64 + lane], cm2 * sh_2);
    if (lane == 0) atomicAdd(&g_cnt[dst], 1.f);
}

// ---------------- stage-1 mean -------------------------------------------------

__global__ void k_norm1(int N) {
    int idx = blockIdx.x * blockDim.x + threadIdx.x;
    if (idx >= N * 32) return;
    int n = idx >> 5, u = idx & 31;
    float inv = 1.f / fmaxf(g_cnt[n], 1.f);
    g_s[idx] *= inv;
    g_v[n * 96 +      u] *= inv;
    g_v[n * 96 + 32 + u] *= inv;
    g_v[n * 96 + 64 + u] *= inv;
}

// ---------------- per-node precontraction of ly weights -----------------------
// G[n][k=0..8][2 float4 rows][32 w]: {Y0,Y1,Z2_0,Z2_1} {Z2_2,Z3_0,Z3_1,Z3_2}
__global__ void __launch_bounds__(256)
k_pre_ly(const float* __restrict__ W1, const float* __restrict__ B1, int N) {
    __shared__ float s_sm[32][32];
    __shared__ float v_sm[32][96];   // plane layout [i*32+u]
    int tid = threadIdx.x;
    int w = tid & 31;
    int q = tid >> 5;
    int nb = blockIdx.x * 32;

    for (int i = tid; i < 32 * 32; i += 256) {
        int n = nb + (i >> 5);
        s_sm[i >> 5][i & 31] = (n < N) ? g_s[n * 32 + (i & 31)] : 0.f;
    }
    for (int i = tid; i < 32 * 96; i += 256) {
        int n = nb + (i / 96);
        v_sm[i / 96][i % 96] = (n < N) ? g_v[n * 96 + (i % 96)] : 0.f;
    }
    __syncthreads();

    int n0 = q * 4;

    for (int k = 0; k < 9; k++) {
        const float* Wk = (k < 8) ? (W1 + k * 4096) : B1;
        float y0[4] = {0.f, 0.f, 0.f, 0.f};
        float y1[4] = {0.f, 0.f, 0.f, 0.f};
        float z2[4][3] = {};
        float z3[4][3] = {};
#pragma unroll 4
        for (int u = 0; u < 32; u++) {
            float w0 = Wk[           u * 32 + w];
            float w1 = Wk[1024 +     u * 32 + w];
            float w2 = Wk[2048 +     u * 32 + w];
            float w3 = Wk[3072 +     u * 32 + w];
#pragma unroll
            for (int nn = 0; nn < 4; nn++) {
                float su = s_sm[n0 + nn][u];
                float v0 = v_sm[n0 + nn][     u];
                float v1 = v_sm[n0 + nn][32 + u];
                float v2 = v_sm[n0 + nn][64 + u];
                y0[nn] += su * w0;
                y1[nn] += su * w1;
                z2[nn][0] += v0 * w2;  z2[nn][1] += v1 * w2;  z2[nn][2] += v2 * w2;
                z3[nn][0] += v0 * w3;  z3[nn][1] += v1 * w3;  z3[nn][2] += v2 * w3;
            }
        }
#pragma unroll
        for (int nn = 0; nn < 4; nn++) {
            int n = nb + n0 + nn;
            if (n < N) {
                float4* Gp = reinterpret_cast<float4*>(&g_G[n * 2304]);
                Gp[(2 * k + 0) * 32 + w] = make_float4(y0[nn], y1[nn], z2[nn][0], z2[nn][1]);
                Gp[(2 * k + 1) * 32 + w] = make_float4(z2[nn][2], z3[nn][0], z3[nn][1], z3[nn][2]);
            }
        }
    }
}

// ---------------- apply ly: warp per src node, G in regs, atomic scatter ------
__global__ void __launch_bounds__(128)
k_apply_ly(const int* __restrict__ ei, int N, int E) {
    int lane = threadIdx.x & 31;
    int n = blockIdx.x * 4 + (threadIdx.x >> 5);
    if (n >= N) return;
    int beg = g_off_s[n], end = g_off_s[n + 1];
    if (beg == end) return;

    const float4* Gp = reinterpret_cast<const float4*>(&g_G[n * 2304]);
    float4 Ga[9], Gb[9];
#pragma unroll
    for (int k = 0; k < 9; k++) {
        Ga[k] = Gp[(2 * k + 0) * 32 + lane];
        Gb[k] = Gp[(2 * k + 1) * 32 + lane];
    }

    for (int p = beg; p < end; p++) {
        int e = g_csr_s[p];
        int dst = ei[E + e];
        float sh_0 = g_sh1[e * 3 + 0], sh_1 = g_sh1[e * 3 + 1], sh_2 = g_sh1[e * 3 + 2];
        const float4* hp = reinterpret_cast<const float4*>(&g_hly[e * 8]);
        float4 ha = hp[0], hb = hp[1];
        float h[9] = {ha.x, ha.y, ha.z, ha.w, hb.x, hb.y, hb.z, hb.w, 1.0f};

        float ys = 0.f, yv = 0.f;
        float z20 = 0.f, z21 = 0.f, z22 = 0.f;
        float z30 = 0.f, z31 = 0.f, z32 = 0.f;
#pragma unroll
        for (int k = 0; k < 9; k++) {
            float hk = h[k];
            ys  += hk * Ga[k].x;  yv  += hk * Ga[k].y;
            z20 += hk * Ga[k].z;  z21 += hk * Ga[k].w;
            z22 += hk * Gb[k].x;
            z30 += hk * Gb[k].y;  z31 += hk * Gb[k].z;  z32 += hk * Gb[k].w;
        }
        float out_s = ys + INV_SQRT3 * (sh_0 * z30 + sh_1 * z31 + sh_2 * z32);
        atomicAdd(&g_cs[dst * 32 + lane],      C_LY * out_s);
        atomicAdd(&g_cv[dst * 96 +      lane], C_LY * (sh_0 * yv + z20));
        atomicAdd(&g_cv[dst * 96 + 32 + lane], C_LY * (sh_1 * yv + z21));
        atomicAdd(&g_cv[dst * 96 + 64 + lane], C_LY * (sh_2 * yv + z22));
    }
}

// ---------------- conv mean + linear self-interaction -------------------------
__global__ void k_norm2(const float* __restrict__ Ws, const float* __restrict__ Wv, int N) {
    int lane = threadIdx.x & 31;
    int n = blockIdx.x * (blockDim.x >> 5) + (threadIdx.x >> 5);
    if (n >= N) return;
    float inv = 1.f / fmaxf(g_cnt[n], 1.f);
    float sl  = g_s[n * 32 + lane];
    float vl0 = g_v[n * 96 +      lane];
    float vl1 = g_v[n * 96 + 32 + lane];
    float vl2 = g_v[n * 96 + 64 + lane];
    float ls = 0.f, lv0 = 0.f, lv1 = 0.f, lv2 = 0.f;
#pragma unroll 4
    for (int u = 0; u < 32; u++) {
        float su  = __shfl_sync(FULLMASK, sl,  u);
        float vu0 = __shfl_sync(FULLMASK, vl0, u);
        float vu1 = __shfl_sync(FULLMASK, vl1, u);
        float vu2 = __shfl_sync(FULLMASK, vl2, u);
        float ws = Ws[u * 32 + lane];
        float wv = Wv[u * 32 + lane];
        ls  += su  * ws;
        lv0 += vu0 * wv;
        lv1 += vu1 * wv;
        lv2 += vu2 * wv;
    }
    g_s2[n * 32 + lane]      = g_cs[n * 32 + lane] * inv      + LC * ls;
    g_v2[n * 96 +      lane] = g_cv[n * 96 +      lane] * inv + LC * lv0;
    g_v2[n * 96 + 32 + lane] = g_cv[n * 96 + 32 + lane] * inv + LC * lv1;
    g_v2[n * 96 + 64 + lane] = g_cv[n * 96 + 64 + lane] * inv + LC * lv2;
}

// ---------------- edge output tensor product ----------------------------------
__global__ void k_et(const float* __restrict__ W1, const float* __restrict__ B1,
                     const int* __restrict__ ei, float* __restrict__ out, int E) {
    __shared__ float sW[8 * 640];
    __shared__ float sB[640];
    for (int i = threadIdx.x; i < 8 * 640; i += blockDim.x) sW[i] = W1[i];
    for (int i = threadIdx.x; i < 640;     i += blockDim.x) sB[i] = B1[i];
    __syncthreads();

    int lane = threadIdx.x & 31;   // = u
    int e = blockIdx.x * (blockDim.x >> 5) + (threadIdx.x >> 5);
    if (e >= E) return;
    int src = ei[e], dst = ei[E + e];
    float sh_0 = g_sh1[e * 3 + 0], sh_1 = g_sh1[e * 3 + 1], sh_2 = g_sh1[e * 3 + 2];
    const float4* hp = reinterpret_cast<const float4*>(&g_het[e * 8]);
    float4 ha = hp[0], hb = hp[1];
    float h[8] = {ha.x, ha.y, ha.z, ha.w, hb.x, hb.y, hb.z, hb.w};

    float x[4];
    x[0] = g_s2[src * 32 + lane];
    {
        float a = g_v2[src * 96 +      lane];
        float b = g_v2[src * 96 + 32 + lane];
        float c = g_v2[src * 96 + 64 + lane];
        x[1] = (a * sh_0 + b * sh_1 + c * sh_2) * INV_SQRT3;
    }
    x[2] = g_s2[dst * 32 + lane];
    {
        float a = g_v2[dst * 96 +      lane];
        float b = g_v2[dst * 96 + 32 + lane];
        float c = g_v2[dst * 96 + 64 + lane];
        x[3] = (a * sh_0 + b * sh_1 + c * sh_2) * INV_SQRT3;
    }

    float p0 = 0.f, p1 = 0.f, p2 = 0.f, p3 = 0.f, p4 = 0.f;
#pragma unroll
    for (int P = 0; P < 4; P++) {
        int base = P * 160 + lane * 5;
        float xp = x[P];
#pragma unroll
        for (int w = 0; w < 5; w++) {
            float wt = sB[base + w];
#pragma unroll
            for (int k = 0; k < 8; k++) wt += h[k] * sW[k * 640 + base + w];
            float contrib = xp * wt;
            if (w == 0) p0 += contrib;
            else if (w == 1) p1 += contrib;
            else if (w == 2) p2 += contrib;
            else if (w == 3) p3 += contrib;
            else p4 += contrib;
        }
    }
#pragma unroll
    for (int off = 16; off > 0; off >>= 1) {
        p0 += __shfl_xor_sync(FULLMASK, p0, off);
        p1 += __shfl_xor_sync(FULLMASK, p1, off);
        p2 += __shfl_xor_sync(FULLMASK, p2, off);
        p3 += __shfl_xor_sync(FULLMASK, p3, off);
        p4 += __shfl_xor_sync(FULLMASK, p4, off);
    }
    if (lane == 0) {
        out[e * 5 + 0] = C_ET * p0;
        out[e * 5 + 1] = C_ET * p1;
        out[e * 5 + 2] = C_ET * p2;
        out[e * 5 + 3] = C_ET * p3;
        out[e * 5 + 4] = C_ET * p4;
    }
}

// ---------------- node output MLP ---------------------------------------------
__global__ void k_nodeout(const float* __restrict__ W1, const float* __restrict__ W2,
                          float* __restrict__ out, int N) {
    int n = blockIdx.x * blockDim.x + threadIdx.x;
    if (n >= N) return;
    float s[32];
#pragma unroll
    for (int u = 0; u < 32; u++) s[u] = g_s2[n * 32 + u];
    float h[13];
#pragma unroll
    for (int j = 0; j < 13; j++) {
        float pre = 0.f;
#pragma unroll
        for (int u = 0; u < 32; u++) pre += s[u] * W1[u * 13 + j];
        pre *= INV_SQRT32;
        h[j] = siluf(pre);
    }
#pragma unroll
    for (int j2 = 0; j2 < 13; j2++) {
        float o = 0.f;
#pragma unroll
        for (int j = 0; j < 13; j++) o += h[j] * W2[j * 13 + j2];
        out[n * 13 + j2] = o * INV_SQRT13;
    }
}

// ---------------- launch ------------------------------------------------------

extern "C" void kernel_launch(void* const* d_in, const int* in_sizes, int n_in,
                              void* d_out, int out_size) {
    const float* coords     = (const float*)d_in[0];
    const int*   atom_types = (const int*)  d_in[1];
    const int*   ei         = (const int*)  d_in[2];
    const float* atom_embed = (const float*)d_in[3];
    const float* ip_W0 = (const float*)d_in[4];
    const float* ip_b0 = (const float*)d_in[5];
    const float* ip_W1 = (const float*)d_in[6];
    const float* ip_b1 = (const float*)d_in[7];
    const float* ly_W0 = (const float*)d_in[8];
    const float* ly_b0 = (const float*)d_in[9];
    const float* ly_W1 = (const float*)d_in[10];
    const float* ly_b1 = (const float*)d_in[11];
    const float* ly_Ws = (const float*)d_in[12];
    const float* ly_Wv = (const float*)d_in[13];
    const float* et_W0 = (const float*)d_in[14];
    const float* et_b0 = (const float*)d_in[15];
    const float* et_W1 = (const float*)d_in[16];
    const float* et_b1 = (const float*)d_in[17];
    const float* no_W1 = (const float*)d_in[18];
    const float* no_W2 = (const float*)d_in[19];
    float* out = (float*)d_out;

    int N = in_sizes[0] / 3;   // 5000
    int E = in_sizes[2] / 2;   // 40000

    k_zero<<<256, 256>>>(N);
    k_pretype<<<100, 32>>>(atom_embed, ip_W1, ip_b1);
    k_hist_s<<<(E + 255) / 256, 256>>>(ei, E);
    k_scan_s<<<1, 1024>>>(N);
    k_fill_s<<<(E + 255) / 256, 256>>>(ei, E);
    k_edge1<<<(E + 7) / 8, 256>>>(coords, atom_types, ei,
                                  ip_W0, ip_b0, ly_W0, ly_b0, et_W0, et_b0, E);
    k_norm1<<<(N * 32 + 255) / 256, 256>>>(N);
    k_pre_ly<<<(N + 31) / 32, 256>>>(ly_W1, ly_b1, N);
    k_apply_ly<<<(N + 3) / 4, 128>>>(ei, N, E);
    k_norm2<<<(N + 7) / 8, 256>>>(ly_Ws, ly_Wv, N);
    k_et<<<(E + 7) / 8, 256>>>(et_W1, et_b1, ei, out, E);
    k_nodeout<<<(N + 127) / 128, 128>>>(no_W1, no_W2, out + (size_t)E * 5, N);
}

// round 9
// speedup vs baseline: 1.7209x; 1.2158x over previous
#include <cuda_runtime.h>
#include <math.h>

#define NN 5000
#define EE 40000

// ---------------- scratch (device globals) -----------------------------------
__device__ float g_sh1[EE * 3];    // sqrt3 * (ny, nz, nx)
__device__ float g_hly[EE * 8];    // hidden activations of ly MLP
__device__ float g_het[EE * 8];    // hidden activations of et MLP
__device__ float g_s  [NN * 32];   // stage-1 node scalars (RAW sums; divide on read)
__device__ float g_v  [NN * 96];   // stage-1 node vectors, plane layout [i*32+u] (RAW)
__device__ float g_cs [NN * 32];   // layer conv scalar accum
__device__ float g_cv [NN * 96];   // layer conv vector accum, plane layout
__device__ float g_s2 [NN * 32];   // final node scalars
__device__ float g_v2 [NN * 96];   // final node vectors, plane layout
__device__ float g_cnt[NN];        // in-degree (dst)
__device__ float g_A1 [100 * 9 * 32];
__device__ float g_A2 [100 * 9 * 32];
__device__ float g_G  [NN * 2304]; // per-node precontracted ly weights
// src-CSR
__device__ int g_deg_s[NN];
__device__ int g_off_s[NN + 1];
__device__ int g_cur_s[NN];
__device__ int g_csr_s[EE];

#define FULLMASK 0xffffffffu
__device__ __forceinline__ float siluf(float x) { return x / (1.f + __expf(-x)); }

constexpr float SQRT3      = 1.7320508075688772f;
constexpr float INV_SQRT3  = 0.57735026918962576f;
constexpr float C_IP       = 0.17677669529663687f;  // 1/sqrt(32)
constexpr float C_LY       = 0.125f;                // 1/sqrt(64)
constexpr float C_ET       = 0.08838834764831843f;  // 1/sqrt(128)
constexpr float LC         = 0.17677669529663687f;  // o3.Linear norm 1/sqrt(32)
constexpr float INV_SQRT32 = 0.17677669529663687f;
constexpr float INV_SQRT13 = 0.27735009811261457f;
constexpr float CUTOFF     = 5.0f;

// ---------------- fused init: pretype (blocks 0..99) + zero (blocks 100+) -----
__global__ void k_init(const float* __restrict__ emb,
                       const float* __restrict__ ipW1,
                       const float* __restrict__ ipb1, int N) {
    if (blockIdx.x < 100) {
        int t = blockIdx.x;
        int wid = threadIdx.x >> 5;
        int lane = threadIdx.x & 31;
        float e[32];
#pragma unroll
        for (int u = 0; u < 32; u++) e[u] = emb[t * 32 + u];
        {
            int k = wid;  // 8 warps -> k = 0..7
            float a1 = 0.f, a2 = 0.f;
#pragma unroll
            for (int u = 0; u < 32; u++) {
                a1 += e[u] * ipW1[k * 2048 +        u * 32 + lane];
                a2 += e[u] * ipW1[k * 2048 + 1024 + u * 32 + lane];
            }
            g_A1[t * 288 + k * 32 + lane] = a1;
            g_A2[t * 288 + k * 32 + lane] = a2;
        }
        if (wid == 0) {  // bias row
            float b1 = 0.f, b2 = 0.f;
#pragma unroll
            for (int u = 0; u < 32; u++) {
                b1 += e[u] * ipb1[       u * 32 + lane];
                b2 += e[u] * ipb1[1024 + u * 32 + lane];
            }
            g_A1[t * 288 + 8 * 32 + lane] = b1;
            g_A2[t * 288 + 8 * 32 + lane] = b2;
        }
        return;
    }
    int tid = (blockIdx.x - 100) * blockDim.x + threadIdx.x;
    int stride = (gridDim.x - 100) * blockDim.x;
    for (int i = tid; i < N * 32; i += stride) { g_s[i] = 0.f; g_cs[i] = 0.f; }
    for (int i = tid; i < N * 96; i += stride) { g_v[i] = 0.f; g_cv[i] = 0.f; }
    for (int i = tid; i < N;      i += stride) { g_cnt[i] = 0.f; g_deg_s[i] = 0; }
}

// ---------------- per-edge geometry + radial MLPs + stage-1 scatter + hist ----
__global__ void k_edge1(const float* __restrict__ coords,
                        const int*   __restrict__ atom_types,
                        const int*   __restrict__ ei,
                        const float* __restrict__ ipW0, const float* __restrict__ ipb0,
                        const float* __restrict__ lyW0, const float* __restrict__ lyb0,
                        const float* __restrict__ etW0, const float* __restrict__ etb0,
                        int E) {
    int lane = threadIdx.x & 31;
    int e = blockIdx.x * (blockDim.x >> 5) + (threadIdx.x >> 5);
    if (e >= E) return;
    int src = ei[e], dst = ei[E + e];

    float dx = coords[dst * 3 + 0] - coords[src * 3 + 0];
    float dy = coords[dst * 3 + 1] - coords[src * 3 + 1];
    float dz = coords[dst * 3 + 2] - coords[src * 3 + 2];
    float d  = sqrtf(dx * dx + dy * dy + dz * dz + 1e-12f);
    float inv_d = 1.f / d;
    float nx = dx * inv_d, ny = dy * inv_d, nz = dz * inv_d;
    float sh_0 = SQRT3 * ny, sh_1 = SQRT3 * nz, sh_2 = SQRT3 * nx;

    float attr[8];
    constexpr float STEP = CUTOFF / 9.0f;
    constexpr float INV_STEP = 9.0f / CUTOFF;
#pragma unroll
    for (int i = 0; i < 8; i++) {
        float diff = (d - (float)(i + 1) * STEP) * INV_STEP;
        attr[i] = __expf(-diff * diff) * (1.0f / 1.12f);
    }

    int grp = lane >> 3;
    int j   = lane & 7;
    const float* W0 = (grp == 1) ? lyW0 : (grp == 2) ? etW0 : ipW0;
    const float* b0 = (grp == 1) ? lyb0 : (grp == 2) ? etb0 : ipb0;
    float pre = b0[j];
#pragma unroll
    for (int i = 0; i < 8; i++) pre += attr[i] * W0[i * 8 + j];
    float myh = siluf(pre);

    if (grp == 1) g_hly[e * 8 + j] = myh;
    if (grp == 2) g_het[e * 8 + j] = myh;
    if (lane < 3) g_sh1[e * 3 + lane] = (lane == 0) ? sh_0 : (lane == 1) ? sh_1 : sh_2;

    int t = atom_types[src];
    const float* A1 = &g_A1[t * 288];
    const float* A2 = &g_A2[t * 288];
    float m1 = A1[8 * 32 + lane];
    float m2 = A2[8 * 32 + lane];
#pragma unroll
    for (int k = 0; k < 8; k++) {
        float hk = __shfl_sync(FULLMASK, myh, k);
        m1 += hk * A1[k * 32 + lane];
        m2 += hk * A2[k * 32 + lane];
    }
    atomicAdd(&g_s[dst * 32 + lane], C_IP * m1);
    float cm2 = C_IP * m2;
    atomicAdd(&g_v[dst * 96 +      lane], cm2 * sh_0);
    atomicAdd(&g_v[dst * 96 + 32 + lane], cm2 * sh_1);
    atomicAdd(&g_v[dst * 96 + 64 + lane], cm2 * sh_2);
    if (lane == 0) {
        atomicAdd(&g_cnt[dst], 1.f);
        atomicAdd(&g_deg_s[src], 1);
    }
}

// ---------------- single-block scan (shfl two-level) --------------------------
__global__ void k_scan_s(int N) {
    __shared__ int wsum[32];
    int t = threadIdx.x;          // 1024 threads
    int lane = t & 31, wid = t >> 5;
    int base = t * 5;
    int c[5]; int tot = 0;
#pragma unroll
    for (int j = 0; j < 5; j++) {
        c[j] = (base + j < N) ? g_deg_s[base + j] : 0;
        tot += c[j];
    }
    int x = tot;
#pragma unroll
    for (int d = 1; d < 32; d <<= 1) {
        int y = __shfl_up_sync(FULLMASK, x, d);
        if (lane >= d) x += y;
    }
    if (lane == 31) wsum[wid] = x;
    __syncthreads();
    if (wid == 0) {
        int w = wsum[lane];
#pragma unroll
        for (int d = 1; d < 32; d <<= 1) {
            int y = __shfl_up_sync(FULLMASK, w, d);
            if (lane >= d) w += y;
        }
        wsum[lane] = w;
    }
    __syncthreads();
    int run = ((wid > 0) ? wsum[wid - 1] : 0) + x - tot;
#pragma unroll
    for (int j = 0; j < 5; j++) {
        if (base + j < N) { g_off_s[base + j] = run; g_cur_s[base + j] = run; run += c[j]; }
    }
    if (t == 0) g_off_s[N] = wsum[31];
}

// ---------------- fused: CSR fill (blocks 0..156) + pre_ly (blocks 157+) ------
// pre_ly: G[n][k=0..8][2 float4 rows][32 w]; divides g_s/g_v by cnt on load.
__global__ void __launch_bounds__(256)
k_fill_pre(const int* __restrict__ ei,
           const float* __restrict__ W1, const float* __restrict__ B1,
           int N, int E, int FILL_BLOCKS) {
    if ((int)blockIdx.x < FILL_BLOCKS) {
        int e = blockIdx.x * blockDim.x + threadIdx.x;
        if (e < E) {
            int p = atomicAdd(&g_cur_s[ei[e]], 1);
            g_csr_s[p] = e;
        }
        return;
    }
    __shared__ float s_sm[32][32];
    __shared__ float v_sm[32][96];
    int tid = threadIdx.x;
    int w = tid & 31;
    int q = tid >> 5;
    int nb = (blockIdx.x - FILL_BLOCKS) * 32;

    for (int i = tid; i < 32 * 32; i += 256) {
        int n = nb + (i >> 5);
        float inv = (n < N) ? 1.f / fmaxf(g_cnt[n], 1.f) : 0.f;
        s_sm[i >> 5][i & 31] = (n < N) ? g_s[n * 32 + (i & 31)] * inv : 0.f;
    }
    for (int i = tid; i < 32 * 96; i += 256) {
        int n = nb + (i / 96);
        float inv = (n < N) ? 1.f / fmaxf(g_cnt[n], 1.f) : 0.f;
        v_sm[i / 96][i % 96] = (n < N) ? g_v[n * 96 + (i % 96)] * inv : 0.f;
    }
    __syncthreads();

    int n0 = q * 4;

    for (int k = 0; k < 9; k++) {
        const float* Wk = (k < 8) ? (W1 + k * 4096) : B1;
        float y0[4] = {0.f, 0.f, 0.f, 0.f};
        float y1[4] = {0.f, 0.f, 0.f, 0.f};
        float z2[4][3] = {};
        float z3[4][3] = {};
#pragma unroll 4
        for (int u = 0; u < 32; u++) {
            float w0 = Wk[           u * 32 + w];
            float w1 = Wk[1024 +     u * 32 + w];
            float w2 = Wk[2048 +     u * 32 + w];
            float w3 = Wk[3072 +     u * 32 + w];
#pragma unroll
            for (int nn = 0; nn < 4; nn++) {
                float su = s_sm[n0 + nn][u];
                float v0 = v_sm[n0 + nn][     u];
                float v1 = v_sm[n0 + nn][32 + u];
                float v2 = v_sm[n0 + nn][64 + u];
                y0[nn] += su * w0;
                y1[nn] += su * w1;
                z2[nn][0] += v0 * w2;  z2[nn][1] += v1 * w2;  z2[nn][2] += v2 * w2;
                z3[nn][0] += v0 * w3;  z3[nn][1] += v1 * w3;  z3[nn][2] += v2 * w3;
            }
        }
#pragma unroll
        for (int nn = 0; nn < 4; nn++) {
            int n = nb + n0 + nn;
            if (n < N) {
                float4* Gp = reinterpret_cast<float4*>(&g_G[n * 2304]);
                Gp[(2 * k + 0) * 32 + w] = make_float4(y0[nn], y1[nn], z2[nn][0], z2[nn][1]);
                Gp[(2 * k + 1) * 32 + w] = make_float4(z2[nn][2], z3[nn][0], z3[nn][1], z3[nn][2]);
            }
        }
    }
}

// ---------------- apply ly: warp per src node, G in regs, atomic scatter ------
__global__ void __launch_bounds__(128)
k_apply_ly(const int* __restrict__ ei, int N, int E) {
    int lane = threadIdx.x & 31;
    int n = blockIdx.x * 4 + (threadIdx.x >> 5);
    if (n >= N) return;
    int beg = g_off_s[n], end = g_off_s[n + 1];
    if (beg == end) return;

    const float4* Gp = reinterpret_cast<const float4*>(&g_G[n * 2304]);
    float4 Ga[9], Gb[9];
#pragma unroll
    for (int k = 0; k < 9; k++) {
        Ga[k] = Gp[(2 * k + 0) * 32 + lane];
        Gb[k] = Gp[(2 * k + 1) * 32 + lane];
    }

    for (int p = beg; p < end; p++) {
        int e = g_csr_s[p];
        int dst = ei[E + e];
        float sh_0 = g_sh1[e * 3 + 0], sh_1 = g_sh1[e * 3 + 1], sh_2 = g_sh1[e * 3 + 2];
        const float4* hp = reinterpret_cast<const float4*>(&g_hly[e * 8]);
        float4 ha = hp[0], hb = hp[1];
        float h[9] = {ha.x, ha.y, ha.z, ha.w, hb.x, hb.y, hb.z, hb.w, 1.0f};

        float ys = 0.f, yv = 0.f;
        float z20 = 0.f, z21 = 0.f, z22 = 0.f;
        float z30 = 0.f, z31 = 0.f, z32 = 0.f;
#pragma unroll
        for (int k = 0; k < 9; k++) {
            float hk = h[k];
            ys  += hk * Ga[k].x;  yv  += hk * Ga[k].y;
            z20 += hk * Ga[k].z;  z21 += hk * Ga[k].w;
            z22 += hk * Gb[k].x;
            z30 += hk * Gb[k].y;  z31 += hk * Gb[k].z;  z32 += hk * Gb[k].w;
        }
        float out_s = ys + INV_SQRT3 * (sh_0 * z30 + sh_1 * z31 + sh_2 * z32);
        atomicAdd(&g_cs[dst * 32 + lane],      C_LY * out_s);
        atomicAdd(&g_cv[dst * 96 +      lane], C_LY * (sh_0 * yv + z20));
        atomicAdd(&g_cv[dst * 96 + 32 + lane], C_LY * (sh_1 * yv + z21));
        atomicAdd(&g_cv[dst * 96 + 64 + lane], C_LY * (sh_2 * yv + z22));
    }
}

// ---------------- conv mean + linear self-interaction -------------------------
__global__ void k_norm2(const float* __restrict__ Ws, const float* __restrict__ Wv, int N) {
    int lane = threadIdx.x & 31;
    int n = blockIdx.x * (blockDim.x >> 5) + (threadIdx.x >> 5);
    if (n >= N) return;
    float inv = 1.f / fmaxf(g_cnt[n], 1.f);
    float sl  = g_s[n * 32 + lane]      * inv;   // stage-1 mean (raw / cnt)
    float vl0 = g_v[n * 96 +      lane] * inv;
    float vl1 = g_v[n * 96 + 32 + lane] * inv;
    float vl2 = g_v[n * 96 + 64 + lane] * inv;
    float ls = 0.f, lv0 = 0.f, lv1 = 0.f, lv2 = 0.f;
#pragma unroll 4
    for (int u = 0; u < 32; u++) {
        float su  = __shfl_sync(FULLMASK, sl,  u);
        float vu0 = __shfl_sync(FULLMASK, vl0, u);
        float vu1 = __shfl_sync(FULLMASK, vl1, u);
        float vu2 = __shfl_sync(FULLMASK, vl2, u);
        float ws = Ws[u * 32 + lane];
        float wv = Wv[u * 32 + lane];
        ls  += su  * ws;
        lv0 += vu0 * wv;
        lv1 += vu1 * wv;
        lv2 += vu2 * wv;
    }
    g_s2[n * 32 + lane]      = g_cs[n * 32 + lane] * inv      + LC * ls;
    g_v2[n * 96 +      lane] = g_cv[n * 96 +      lane] * inv + LC * lv0;
    g_v2[n * 96 + 32 + lane] = g_cv[n * 96 + 32 + lane] * inv + LC * lv1;
    g_v2[n * 96 + 64 + lane] = g_cv[n * 96 + 64 + lane] * inv + LC * lv2;
}

// ---------------- fused output: et (grid-stride, blocks<ETB) + nodeout --------
__global__ void __launch_bounds__(256)
k_out(const float* __restrict__ W1, const float* __restrict__ B1,
      const int* __restrict__ ei,
      const float* __restrict__ noW1, const float* __restrict__ noW2,
      float* __restrict__ out, int N, int E, int ET_BLOCKS) {
    if ((int)blockIdx.x >= ET_BLOCKS) {
        // ---- node output MLP ----
        int n = (blockIdx.x - ET_BLOCKS) * blockDim.x + threadIdx.x;
        if (n >= N) return;
        float s[32];
#pragma unroll
        for (int u = 0; u < 32; u++) s[u] = g_s2[n * 32 + u];
        float h[13];
#pragma unroll
        for (int j = 0; j < 13; j++) {
            float pre = 0.f;
#pragma unroll
            for (int u = 0; u < 32; u++) pre += s[u] * noW1[u * 13 + j];
            pre *= INV_SQRT32;
            h[j] = siluf(pre);
        }
        float* nout = out + (size_t)E * 5;
#pragma unroll
        for (int j2 = 0; j2 < 13; j2++) {
            float o = 0.f;
#pragma unroll
            for (int j = 0; j < 13; j++) o += h[j] * noW2[j * 13 + j2];
            nout[n * 13 + j2] = o * INV_SQRT13;
        }
        return;
    }
    // ---- edge output tensor product, grid-stride over edges ----
    __shared__ float sW[8 * 640];
    __shared__ float sB[640];
    for (int i = threadIdx.x; i < 8 * 640; i += blockDim.x) sW[i] = W1[i];
    for (int i = threadIdx.x; i < 640;     i += blockDim.x) sB[i] = B1[i];
    __syncthreads();

    int lane = threadIdx.x & 31;   // = u
    int gw = blockIdx.x * 8 + (threadIdx.x >> 5);
    int nwarps = ET_BLOCKS * 8;

    for (int e = gw; e < E; e += nwarps) {
        int src = ei[e], dst = ei[E + e];
        float sh_0 = g_sh1[e * 3 + 0], sh_1 = g_sh1[e * 3 + 1], sh_2 = g_sh1[e * 3 + 2];
        const float4* hp = reinterpret_cast<const float4*>(&g_het[e * 8]);
        float4 ha = hp[0], hb = hp[1];
        float h[8] = {ha.x, ha.y, ha.z, ha.w, hb.x, hb.y, hb.z, hb.w};

        float x[4];
        x[0] = g_s2[src * 32 + lane];
        {
            float a = g_v2[src * 96 +      lane];
            float b = g_v2[src * 96 + 32 + lane];
            float c = g_v2[src * 96 + 64 + lane];
            x[1] = (a * sh_0 + b * sh_1 + c * sh_2) * INV_SQRT3;
        }
        x[2] = g_s2[dst * 32 + lane];
        {
            float a = g_v2[dst * 96 +      lane];
            float b = g_v2[dst * 96 + 32 + lane];
            float c = g_v2[dst * 96 + 64 + lane];
            x[3] = (a * sh_0 + b * sh_1 + c * sh_2) * INV_SQRT3;
        }

        float p0 = 0.f, p1 = 0.f, p2 = 0.f, p3 = 0.f, p4 = 0.f;
#pragma unroll
        for (int P = 0; P < 4; P++) {
            int base = P * 160 + lane * 5;
            float xp = x[P];
#pragma unroll
            for (int w = 0; w < 5; w++) {
                float wt = sB[base + w];
#pragma unroll
                for (int k = 0; k < 8; k++) wt += h[k] * sW[k * 640 + base + w];
                float contrib = xp * wt;
                if (w == 0) p0 += contrib;
                else if (w == 1) p1 += contrib;
                else if (w == 2) p2 += contrib;
                else if (w == 3) p3 += contrib;
                else p4 += contrib;
            }
        }
#pragma unroll
        for (int off = 16; off > 0; off >>= 1) {
            p0 += __shfl_xor_sync(FULLMASK, p0, off);
            p1 += __shfl_xor_sync(FULLMASK, p1, off);
            p2 += __shfl_xor_sync(FULLMASK, p2, off);
            p3 += __shfl_xor_sync(FULLMASK, p3, off);
            p4 += __shfl_xor_sync(FULLMASK, p4, off);
        }
        if (lane == 0) {
            out[e * 5 + 0] = C_ET * p0;
            out[e * 5 + 1] = C_ET * p1;
            out[e * 5 + 2] = C_ET * p2;
            out[e * 5 + 3] = C_ET * p3;
            out[e * 5 + 4] = C_ET * p4;
        }
    }
}

// ---------------- launch ------------------------------------------------------

extern "C" void kernel_launch(void* const* d_in, const int* in_sizes, int n_in,
                              void* d_out, int out_size) {
    const float* coords     = (const float*)d_in[0];
    const int*   atom_types = (const int*)  d_in[1];
    const int*   ei         = (const int*)  d_in[2];
    const float* atom_embed = (const float*)d_in[3];
    const float* ip_W0 = (const float*)d_in[4];
    const float* ip_b0 = (const float*)d_in[5];
    const float* ip_W1 = (const float*)d_in[6];
    const float* ip_b1 = (const float*)d_in[7];
    const float* ly_W0 = (const float*)d_in[8];
    const float* ly_b0 = (const float*)d_in[9];
    const float* ly_W1 = (const float*)d_in[10];
    const float* ly_b1 = (const float*)d_in[11];
    const float* ly_Ws = (const float*)d_in[12];
    const float* ly_Wv = (const float*)d_in[13];
    const float* et_W0 = (const float*)d_in[14];
    const float* et_b0 = (const float*)d_in[15];
    const float* et_W1 = (const float*)d_in[16];
    const float* et_b1 = (const float*)d_in[17];
    const float* no_W1 = (const float*)d_in[18];
    const float* no_W2 = (const float*)d_in[19];
    float* out = (float*)d_out;

    int N = in_sizes[0] / 3;   // 5000
    int E = in_sizes[2] / 2;   // 40000

    const int FILL_BLOCKS = (E + 255) / 256;          // 157
    const int PRE_BLOCKS  = (N + 31) / 32;            // 157
    const int ET_BLOCKS   = 296;
    const int NO_BLOCKS   = (N + 255) / 256;          // 20

    k_init<<<100 + 256, 256>>>(atom_embed, ip_W1, ip_b1, N);
    k_edge1<<<(E + 7) / 8, 256>>>(coords, atom_types, ei,
                                  ip_W0, ip_b0, ly_W0, ly_b0, et_W0, et_b0, E);
    k_scan_s<<<1, 1024>>>(N);
    k_fill_pre<<<FILL_BLOCKS + PRE_BLOCKS, 256>>>(ei, ly_W1, ly_b1, N, E, FILL_BLOCKS);
    k_apply_ly<<<(N + 3) / 4, 128>>>(ei, N, E);
    k_norm2<<<(N + 7) / 8, 256>>>(ly_Ws, ly_Wv, N);
    k_out<<<ET_BLOCKS + NO_BLOCKS, 256>>>(et_W1, et_b1, ei, no_W1, no_W2,
                                          out, N, E, ET_BLOCKS);
}

// round 10
// speedup vs baseline: 1.9326x; 1.1230x over previous
#include <cuda_runtime.h>
#include <math.h>

#define NN 5000
#define EE 40000

// ---------------- scratch (device globals) -----------------------------------
__device__ float g_sh1[EE * 3];    // sqrt3 * (ny, nz, nx)
__device__ float g_hly[EE * 8];    // hidden activations of ly MLP
__device__ float g_het[EE * 8];    // hidden activations of et MLP
__device__ float g_s  [NN * 32];   // stage-1 node scalars (RAW sums; divide on read)
__device__ float g_v  [NN * 96];   // stage-1 node vectors, plane layout [i*32+u] (RAW)
__device__ float g_cs [NN * 32];   // layer conv scalar accum
__device__ float g_cv [NN * 96];   // layer conv vector accum, plane layout
__device__ float g_s2 [NN * 32];   // final node scalars
__device__ float g_v2 [NN * 96];   // final node vectors, plane layout
__device__ float g_cnt[NN];        // in-degree (dst)
__device__ float g_A1 [100 * 9 * 32];
__device__ float g_A2 [100 * 9 * 32];
__device__ float g_G  [NN * 2304]; // per-node precontracted ly weights
// src-CSR
__device__ int g_deg_s[NN];
__device__ int g_off_s[NN + 1];
__device__ int g_cur_s[NN];
__device__ int g_csr_s[EE];

#define FULLMASK 0xffffffffu
__device__ __forceinline__ float siluf(float x) { return x / (1.f + __expf(-x)); }

constexpr float SQRT3      = 1.7320508075688772f;
constexpr float INV_SQRT3  = 0.57735026918962576f;
constexpr float C_IP       = 0.17677669529663687f;  // 1/sqrt(32)
constexpr float C_LY       = 0.125f;                // 1/sqrt(64)
constexpr float C_ET       = 0.08838834764831843f;  // 1/sqrt(128)
constexpr float LC         = 0.17677669529663687f;  // o3.Linear norm 1/sqrt(32)
constexpr float INV_SQRT32 = 0.17677669529663687f;
constexpr float INV_SQRT13 = 0.27735009811261457f;
constexpr float CUTOFF     = 5.0f;

// ---------------- fused init: pretype (blocks 0..99) + zero (blocks 100+) -----
__global__ void k_init(const float* __restrict__ emb,
                       const float* __restrict__ ipW1,
                       const float* __restrict__ ipb1, int N) {
    if (blockIdx.x < 100) {
        int t = blockIdx.x;
        int wid = threadIdx.x >> 5;
        int lane = threadIdx.x & 31;
        float e[32];
#pragma unroll
        for (int u = 0; u < 32; u++) e[u] = emb[t * 32 + u];
        {
            int k = wid;  // 8 warps -> k = 0..7
            float a1 = 0.f, a2 = 0.f;
#pragma unroll
            for (int u = 0; u < 32; u++) {
                a1 += e[u] * ipW1[k * 2048 +        u * 32 + lane];
                a2 += e[u] * ipW1[k * 2048 + 1024 + u * 32 + lane];
            }
            g_A1[t * 288 + k * 32 + lane] = a1;
            g_A2[t * 288 + k * 32 + lane] = a2;
        }
        if (wid == 0) {  // bias row
            float b1 = 0.f, b2 = 0.f;
#pragma unroll
            for (int u = 0; u < 32; u++) {
                b1 += e[u] * ipb1[       u * 32 + lane];
                b2 += e[u] * ipb1[1024 + u * 32 + lane];
            }
            g_A1[t * 288 + 8 * 32 + lane] = b1;
            g_A2[t * 288 + 8 * 32 + lane] = b2;
        }
        return;
    }
    int tid = (blockIdx.x - 100) * blockDim.x + threadIdx.x;
    int stride = (gridDim.x - 100) * blockDim.x;
    for (int i = tid; i < N * 32; i += stride) { g_s[i] = 0.f; g_cs[i] = 0.f; }
    for (int i = tid; i < N * 96; i += stride) { g_v[i] = 0.f; g_cv[i] = 0.f; }
    for (int i = tid; i < N;      i += stride) { g_cnt[i] = 0.f; g_deg_s[i] = 0; }
}

// ---------------- per-edge geometry + radial MLPs + stage-1 scatter + hist ----
__global__ void k_edge1(const float* __restrict__ coords,
                        const int*   __restrict__ atom_types,
                        const int*   __restrict__ ei,
                        const float* __restrict__ ipW0, const float* __restrict__ ipb0,
                        const float* __restrict__ lyW0, const float* __restrict__ lyb0,
                        const float* __restrict__ etW0, const float* __restrict__ etb0,
                        int E) {
    int lane = threadIdx.x & 31;
    int e = blockIdx.x * (blockDim.x >> 5) + (threadIdx.x >> 5);
    if (e >= E) return;
    int src = ei[e], dst = ei[E + e];

    float dx = coords[dst * 3 + 0] - coords[src * 3 + 0];
    float dy = coords[dst * 3 + 1] - coords[src * 3 + 1];
    float dz = coords[dst * 3 + 2] - coords[src * 3 + 2];
    float d  = sqrtf(dx * dx + dy * dy + dz * dz + 1e-12f);
    float inv_d = 1.f / d;
    float nx = dx * inv_d, ny = dy * inv_d, nz = dz * inv_d;
    float sh_0 = SQRT3 * ny, sh_1 = SQRT3 * nz, sh_2 = SQRT3 * nx;

    float attr[8];
    constexpr float STEP = CUTOFF / 9.0f;
    constexpr float INV_STEP = 9.0f / CUTOFF;
#pragma unroll
    for (int i = 0; i < 8; i++) {
        float diff = (d - (float)(i + 1) * STEP) * INV_STEP;
        attr[i] = __expf(-diff * diff) * (1.0f / 1.12f);
    }

    int grp = lane >> 3;
    int j   = lane & 7;
    const float* W0 = (grp == 1) ? lyW0 : (grp == 2) ? etW0 : ipW0;
    const float* b0 = (grp == 1) ? lyb0 : (grp == 2) ? etb0 : ipb0;
    float pre = b0[j];
#pragma unroll
    for (int i = 0; i < 8; i++) pre += attr[i] * W0[i * 8 + j];
    float myh = siluf(pre);

    if (grp == 1) g_hly[e * 8 + j] = myh;
    if (grp == 2) g_het[e * 8 + j] = myh;
    if (lane < 3) g_sh1[e * 3 + lane] = (lane == 0) ? sh_0 : (lane == 1) ? sh_1 : sh_2;

    int t = atom_types[src];
    const float* A1 = &g_A1[t * 288];
    const float* A2 = &g_A2[t * 288];
    float m1 = A1[8 * 32 + lane];
    float m2 = A2[8 * 32 + lane];
#pragma unroll
    for (int k = 0; k < 8; k++) {
        float hk = __shfl_sync(FULLMASK, myh, k);
        m1 += hk * A1[k * 32 + lane];
        m2 += hk * A2[k * 32 + lane];
    }
    atomicAdd(&g_s[dst * 32 + lane], C_IP * m1);
    float cm2 = C_IP * m2;
    atomicAdd(&g_v[dst * 96 +      lane], cm2 * sh_0);
    atomicAdd(&g_v[dst * 96 + 32 + lane], cm2 * sh_1);
    atomicAdd(&g_v[dst * 96 + 64 + lane], cm2 * sh_2);
    if (lane == 0) {
        atomicAdd(&g_cnt[dst], 1.f);
        atomicAdd(&g_deg_s[src], 1);
    }
}

// ---------------- single-block scan (shfl two-level) --------------------------
__global__ void k_scan_s(int N) {
    __shared__ int wsum[32];
    int t = threadIdx.x;          // 1024 threads
    int lane = t & 31, wid = t >> 5;
    int base = t * 5;
    int c[5]; int tot = 0;
#pragma unroll
    for (int j = 0; j < 5; j++) {
        c[j] = (base + j < N) ? g_deg_s[base + j] : 0;
        tot += c[j];
    }
    int x = tot;
#pragma unroll
    for (int d = 1; d < 32; d <<= 1) {
        int y = __shfl_up_sync(FULLMASK, x, d);
        if (lane >= d) x += y;
    }
    if (lane == 31) wsum[wid] = x;
    __syncthreads();
    if (wid == 0) {
        int w = wsum[lane];
#pragma unroll
        for (int d = 1; d < 32; d <<= 1) {
            int y = __shfl_up_sync(FULLMASK, w, d);
            if (lane >= d) w += y;
        }
        wsum[lane] = w;
    }
    __syncthreads();
    int run = ((wid > 0) ? wsum[wid - 1] : 0) + x - tot;
#pragma unroll
    for (int j = 0; j < 5; j++) {
        if (base + j < N) { g_off_s[base + j] = run; g_cur_s[base + j] = run; run += c[j]; }
    }
    if (t == 0) g_off_s[N] = wsum[31];
}

// ---------------- fused: CSR fill + pre_ly (2 nodes/thread, k-split x3) -------
// pre block bb: kseg = bb % 3 handles k in [kseg*3, kseg*3+3); nodes nb..nb+15.
// G[n][k][2 float4 rows][32 w]: {Y0,Y1,Z2_0,Z2_1} {Z2_2,Z3_0,Z3_1,Z3_2}
__global__ void __launch_bounds__(256)
k_fill_pre(const int* __restrict__ ei,
           const float* __restrict__ W1, const float* __restrict__ B1,
           int N, int E, int FILL_BLOCKS) {
    if ((int)blockIdx.x < FILL_BLOCKS) {
        int e = blockIdx.x * blockDim.x + threadIdx.x;
        if (e < E) {
            int p = atomicAdd(&g_cur_s[ei[e]], 1);
            g_csr_s[p] = e;
        }
        return;
    }
    __shared__ float s_sm[16][32];
    __shared__ float v_sm[16][96];
    int tid = threadIdx.x;
    int bb = blockIdx.x - FILL_BLOCKS;
    int kseg = bb % 3;             // k range [kseg*3, kseg*3+3)
    int nb = (bb / 3) * 16;        // 16 nodes per block

    for (int i = tid; i < 16 * 32; i += 256) {
        int n = nb + (i >> 5);
        float val = 0.f;
        if (n < N) val = g_s[n * 32 + (i & 31)] / fmaxf(g_cnt[n], 1.f);
        s_sm[i >> 5][i & 31] = val;
    }
    for (int i = tid; i < 16 * 96; i += 256) {
        int n = nb + (i / 96);
        float val = 0.f;
        if (n < N) val = g_v[n * 96 + (i % 96)] / fmaxf(g_cnt[n], 1.f);
        v_sm[i / 96][i % 96] = val;
    }
    __syncthreads();

    int w = tid & 31;
    int q = tid >> 5;
    int n0 = q * 2;                // 2 nodes per thread

#pragma unroll
    for (int kk = 0; kk < 3; kk++) {
        int k = kseg * 3 + kk;
        const float* Wk = (k < 8) ? (W1 + k * 4096) : B1;
        float y0[2] = {0.f, 0.f};
        float y1[2] = {0.f, 0.f};
        float z2[2][3] = {};
        float z3[2][3] = {};
#pragma unroll 8
        for (int u = 0; u < 32; u++) {
            float w0 = __ldg(&Wk[           u * 32 + w]);
            float w1 = __ldg(&Wk[1024 +     u * 32 + w]);
            float w2 = __ldg(&Wk[2048 +     u * 32 + w]);
            float w3 = __ldg(&Wk[3072 +     u * 32 + w]);
#pragma unroll
            for (int nn = 0; nn < 2; nn++) {
                float su = s_sm[n0 + nn][u];
                float v0 = v_sm[n0 + nn][     u];
                float v1 = v_sm[n0 + nn][32 + u];
                float v2 = v_sm[n0 + nn][64 + u];
                y0[nn] += su * w0;
                y1[nn] += su * w1;
                z2[nn][0] += v0 * w2;  z2[nn][1] += v1 * w2;  z2[nn][2] += v2 * w2;
                z3[nn][0] += v0 * w3;  z3[nn][1] += v1 * w3;  z3[nn][2] += v2 * w3;
            }
        }
#pragma unroll
        for (int nn = 0; nn < 2; nn++) {
            int n = nb + n0 + nn;
            if (n < N) {
                float4* Gp = reinterpret_cast<float4*>(&g_G[n * 2304]);
                Gp[(2 * k + 0) * 32 + w] = make_float4(y0[nn], y1[nn], z2[nn][0], z2[nn][1]);
                Gp[(2 * k + 1) * 32 + w] = make_float4(z2[nn][2], z3[nn][0], z3[nn][1], z3[nn][2]);
            }
        }
    }
}

// ---------------- apply ly: warp per src node, G in regs, atomic scatter ------
__global__ void __launch_bounds__(128)
k_apply_ly(const int* __restrict__ ei, int N, int E) {
    int lane = threadIdx.x & 31;
    int n = blockIdx.x * 4 + (threadIdx.x >> 5);
    if (n >= N) return;
    int beg = g_off_s[n], end = g_off_s[n + 1];
    if (beg == end) return;

    const float4* Gp = reinterpret_cast<const float4*>(&g_G[n * 2304]);
    float4 Ga[9], Gb[9];
#pragma unroll
    for (int k = 0; k < 9; k++) {
        Ga[k] = Gp[(2 * k + 0) * 32 + lane];
        Gb[k] = Gp[(2 * k + 1) * 32 + lane];
    }

    for (int p = beg; p < end; p++) {
        int e = g_csr_s[p];
        int dst = ei[E + e];
        float sh_0 = g_sh1[e * 3 + 0], sh_1 = g_sh1[e * 3 + 1], sh_2 = g_sh1[e * 3 + 2];
        const float4* hp = reinterpret_cast<const float4*>(&g_hly[e * 8]);
        float4 ha = hp[0], hb = hp[1];
        float h[9] = {ha.x, ha.y, ha.z, ha.w, hb.x, hb.y, hb.z, hb.w, 1.0f};

        float ys = 0.f, yv = 0.f;
        float z20 = 0.f, z21 = 0.f, z22 = 0.f;
        float z30 = 0.f, z31 = 0.f, z32 = 0.f;
#pragma unroll
        for (int k = 0; k < 9; k++) {
            float hk = h[k];
            ys  += hk * Ga[k].x;  yv  += hk * Ga[k].y;
            z20 += hk * Ga[k].z;  z21 += hk * Ga[k].w;
            z22 += hk * Gb[k].x;
            z30 += hk * Gb[k].y;  z31 += hk * Gb[k].z;  z32 += hk * Gb[k].w;
        }
        float out_s = ys + INV_SQRT3 * (sh_0 * z30 + sh_1 * z31 + sh_2 * z32);
        atomicAdd(&g_cs[dst * 32 + lane],      C_LY * out_s);
        atomicAdd(&g_cv[dst * 96 +      lane], C_LY * (sh_0 * yv + z20));
        atomicAdd(&g_cv[dst * 96 + 32 + lane], C_LY * (sh_1 * yv + z21));
        atomicAdd(&g_cv[dst * 96 + 64 + lane], C_LY * (sh_2 * yv + z22));
    }
}

// ---------------- conv mean + linear self-interaction -------------------------
__global__ void k_norm2(const float* __restrict__ Ws, const float* __restrict__ Wv, int N) {
    int lane = threadIdx.x & 31;
    int n = blockIdx.x * (blockDim.x >> 5) + (threadIdx.x >> 5);
    if (n >= N) return;
    float inv = 1.f / fmaxf(g_cnt[n], 1.f);
    float sl  = g_s[n * 32 + lane]      * inv;
    float vl0 = g_v[n * 96 +      lane] * inv;
    float vl1 = g_v[n * 96 + 32 + lane] * inv;
    float vl2 = g_v[n * 96 + 64 + lane] * inv;
    float ls = 0.f, lv0 = 0.f, lv1 = 0.f, lv2 = 0.f;
#pragma unroll 4
    for (int u = 0; u < 32; u++) {
        float su  = __shfl_sync(FULLMASK, sl,  u);
        float vu0 = __shfl_sync(FULLMASK, vl0, u);
        float vu1 = __shfl_sync(FULLMASK, vl1, u);
        float vu2 = __shfl_sync(FULLMASK, vl2, u);
        float ws = Ws[u * 32 + lane];
        float wv = Wv[u * 32 + lane];
        ls  += su  * ws;
        lv0 += vu0 * wv;
        lv1 += vu1 * wv;
        lv2 += vu2 * wv;
    }
    g_s2[n * 32 + lane]      = g_cs[n * 32 + lane] * inv      + LC * ls;
    g_v2[n * 96 +      lane] = g_cv[n * 96 +      lane] * inv + LC * lv0;
    g_v2[n * 96 + 32 + lane] = g_cv[n * 96 + 32 + lane] * inv + LC * lv1;
    g_v2[n * 96 + 64 + lane] = g_cv[n * 96 + 64 + lane] * inv + LC * lv2;
}

// ---------------- fused output: et (grid-stride, blocks<ETB) + nodeout --------
__global__ void __launch_bounds__(256)
k_out(const float* __restrict__ W1, const float* __restrict__ B1,
      const int* __restrict__ ei,
      const float* __restrict__ noW1, const float* __restrict__ noW2,
      float* __restrict__ out, int N, int E, int ET_BLOCKS) {
    if ((int)blockIdx.x >= ET_BLOCKS) {
        int n = (blockIdx.x - ET_BLOCKS) * blockDim.x + threadIdx.x;
        if (n >= N) return;
        float s[32];
#pragma unroll
        for (int u = 0; u < 32; u++) s[u] = g_s2[n * 32 + u];
        float h[13];
#pragma unroll
        for (int j = 0; j < 13; j++) {
            float pre = 0.f;
#pragma unroll
            for (int u = 0; u < 32; u++) pre += s[u] * noW1[u * 13 + j];
            pre *= INV_SQRT32;
            h[j] = siluf(pre);
        }
        float* nout = out + (size_t)E * 5;
#pragma unroll
        for (int j2 = 0; j2 < 13; j2++) {
            float o = 0.f;
#pragma unroll
            for (int j = 0; j < 13; j++) o += h[j] * noW2[j * 13 + j2];
            nout[n * 13 + j2] = o * INV_SQRT13;
        }
        return;
    }
    __shared__ float sW[8 * 640];
    __shared__ float sB[640];
    for (int i = threadIdx.x; i < 8 * 640; i += blockDim.x) sW[i] = W1[i];
    for (int i = threadIdx.x; i < 640;     i += blockDim.x) sB[i] = B1[i];
    __syncthreads();

    int lane = threadIdx.x & 31;   // = u
    int gw = blockIdx.x * 8 + (threadIdx.x >> 5);
    int nwarps = ET_BLOCKS * 8;

    for (int e = gw; e < E; e += nwarps) {
        int src = ei[e], dst = ei[E + e];
        float sh_0 = g_sh1[e * 3 + 0], sh_1 = g_sh1[e * 3 + 1], sh_2 = g_sh1[e * 3 + 2];
        const float4* hp = reinterpret_cast<const float4*>(&g_het[e * 8]);
        float4 ha = hp[0], hb = hp[1];
        float h[8] = {ha.x, ha.y, ha.z, ha.w, hb.x, hb.y, hb.z, hb.w};

        float x[4];
        x[0] = g_s2[src * 32 + lane];
        {
            float a = g_v2[src * 96 +      lane];
            float b = g_v2[src * 96 + 32 + lane];
            float c = g_v2[src * 96 + 64 + lane];
            x[1] = (a * sh_0 + b * sh_1 + c * sh_2) * INV_SQRT3;
        }
        x[2] = g_s2[dst * 32 + lane];
        {
            float a = g_v2[dst * 96 +      lane];
            float b = g_v2[dst * 96 + 32 + lane];
            float c = g_v2[dst * 96 + 64 + lane];
            x[3] = (a * sh_0 + b * sh_1 + c * sh_2) * INV_SQRT3;
        }

        float p0 = 0.f, p1 = 0.f, p2 = 0.f, p3 = 0.f, p4 = 0.f;
#pragma unroll
        for (int P = 0; P < 4; P++) {
            int base = P * 160 + lane * 5;
            float xp = x[P];
#pragma unroll
            for (int w = 0; w < 5; w++) {
                float wt = sB[base + w];
#pragma unroll
                for (int k = 0; k < 8; k++) wt += h[k] * sW[k * 640 + base + w];
                float contrib = xp * wt;
                if (w == 0) p0 += contrib;
                else if (w == 1) p1 += contrib;
                else if (w == 2) p2 += contrib;
                else if (w == 3) p3 += contrib;
                else p4 += contrib;
            }
        }
#pragma unroll
        for (int off = 16; off > 0; off >>= 1) {
            p0 += __shfl_xor_sync(FULLMASK, p0, off);
            p1 += __shfl_xor_sync(FULLMASK, p1, off);
            p2 += __shfl_xor_sync(FULLMASK, p2, off);
            p3 += __shfl_xor_sync(FULLMASK, p3, off);
            p4 += __shfl_xor_sync(FULLMASK, p4, off);
        }
        if (lane == 0) {
            out[e * 5 + 0] = C_ET * p0;
            out[e * 5 + 1] = C_ET * p1;
            out[e * 5 + 2] = C_ET * p2;
            out[e * 5 + 3] = C_ET * p3;
            out[e * 5 + 4] = C_ET * p4;
        }
    }
}

// ---------------- launch ------------------------------------------------------

extern "C" void kernel_launch(void* const* d_in, const int* in_sizes, int n_in,
                              void* d_out, int out_size) {
    const float* coords     = (const float*)d_in[0];
    const int*   atom_types = (const int*)  d_in[1];
    const int*   ei         = (const int*)  d_in[2];
    const float* atom_embed = (const float*)d_in[3];
    const float* ip_W0 = (const float*)d_in[4];
    const float* ip_b0 = (const float*)d_in[5];
    const float* ip_W1 = (const float*)d_in[6];
    const float* ip_b1 = (const float*)d_in[7];
    const float* ly_W0 = (const float*)d_in[8];
    const float* ly_b0 = (const float*)d_in[9];
    const float* ly_W1 = (const float*)d_in[10];
    const float* ly_b1 = (const float*)d_in[11];
    const float* ly_Ws = (const float*)d_in[12];
    const float* ly_Wv = (const float*)d_in[13];
    const float* et_W0 = (const float*)d_in[14];
    const float* et_b0 = (const float*)d_in[15];
    const float* et_W1 = (const float*)d_in[16];
    const float* et_b1 = (const float*)d_in[17];
    const float* no_W1 = (const float*)d_in[18];
    const float* no_W2 = (const float*)d_in[19];
    float* out = (float*)d_out;

    int N = in_sizes[0] / 3;   // 5000
    int E = in_sizes[2] / 2;   // 40000

    const int FILL_BLOCKS = (E + 255) / 256;          // 157
    const int PRE_BLOCKS  = 3 * ((N + 15) / 16);      // 3 k-segments x 313
    const int ET_BLOCKS   = 296;
    const int NO_BLOCKS   = (N + 255) / 256;          // 20

    k_init<<<100 + 256, 256>>>(atom_embed, ip_W1, ip_b1, N);
    k_edge1<<<(E + 7) / 8, 256>>>(coords, atom_types, ei,
                                  ip_W0, ip_b0, ly_W0, ly_b0, et_W0, et_b0, E);
    k_scan_s<<<1, 1024>>>(N);
    k_fill_pre<<<FILL_BLOCKS + PRE_BLOCKS, 256>>>(ei, ly_W1, ly_b1, N, E, FILL_BLOCKS);
    k_apply_ly<<<(N + 3) / 4, 128>>>(ei, N, E);
    k_norm2<<<(N + 7) / 8, 256>>>(ly_Ws, ly_Wv, N);
    k_out<<<ET_BLOCKS + NO_BLOCKS, 256>>>(et_W1, et_b1, ei, no_W1, no_W2,
                                          out, N, E, ET_BLOCKS);
}

// round 13
// speedup vs baseline: 1.9730x; 1.0209x over previous
#include <cuda_runtime.h>
#include <math.h>

#define NN 5000
#define EE 40000

typedef unsigned long long ull;

// ---------------- scratch (device globals) -----------------------------------
__device__ float g_sh1[EE * 3];    // sqrt3 * (ny, nz, nx)
__device__ float g_hly[EE * 8];    // hidden activations of ly MLP
__device__ float g_het[EE * 8];    // hidden activations of et MLP
__device__ float g_s  [NN * 32];   // stage-1 node scalars (RAW sums; divide on read)
__device__ float g_v  [NN * 96];   // stage-1 node vectors, plane layout [i*32+u] (RAW)
__device__ float g_cs [NN * 32];   // layer conv scalar accum
__device__ float g_cv [NN * 96];   // layer conv vector accum, plane layout
__device__ float g_s2 [NN * 32];   // final node scalars
__device__ float g_v2 [NN * 96];   // final node vectors, plane layout
__device__ float g_cnt[NN];        // in-degree (dst)
__device__ float2 g_A12[100 * 9 * 32]; // per-type ip contraction, (a1,a2) interleaved
__device__ float g_G  [NN * 2304]; // per-node precontracted ly weights
// src-CSR
__device__ int g_deg_s[NN];
__device__ int g_off_s[NN + 1];
__device__ int g_cur_s[NN];
__device__ int g_csr_s[EE];

#define FULLMASK 0xffffffffu
__device__ __forceinline__ float siluf(float x) { return x / (1.f + __expf(-x)); }

// ---- packed f32x2 helpers (Blackwell dual-FP32 pipe) ----
__device__ __forceinline__ ull pack2(float lo, float hi) {
    ull r; asm("mov.b64 %0, {%1, %2};" : "=l"(r) : "f"(lo), "f"(hi)); return r;
}
__device__ __forceinline__ void unpack2(ull v, float& lo, float& hi) {
    asm("mov.b64 {%0, %1}, %2;" : "=f"(lo), "=f"(hi) : "l"(v));
}
__device__ __forceinline__ ull fma2(ull a, ull b, ull c) {
    ull d; asm("fma.rn.f32x2 %0, %1, %2, %3;" : "=l"(d) : "l"(a), "l"(b), "l"(c)); return d;
}

constexpr float SQRT3      = 1.7320508075688772f;
constexpr float INV_SQRT3  = 0.57735026918962576f;
constexpr float C_IP       = 0.17677669529663687f;  // 1/sqrt(32)
constexpr float C_LY       = 0.125f;                // 1/sqrt(64)
constexpr float C_ET       = 0.08838834764831843f;  // 1/sqrt(128)
constexpr float LC         = 0.17677669529663687f;  // o3.Linear norm 1/sqrt(32)
constexpr float INV_SQRT32 = 0.17677669529663687f;
constexpr float INV_SQRT13 = 0.27735009811261457f;
constexpr float CUTOFF     = 5.0f;

// ---------------- fused init: pretype (blocks 0..99) + zero (blocks 100+) -----
__global__ void k_init(const float* __restrict__ emb,
                       const float* __restrict__ ipW1,
                       const float* __restrict__ ipb1, int N) {
    if (blockIdx.x < 100) {
        int t = blockIdx.x;
        int wid = threadIdx.x >> 5;
        int lane = threadIdx.x & 31;
        float e[32];
#pragma unroll
        for (int u = 0; u < 32; u++) e[u] = emb[t * 32 + u];
        {
            int k = wid;  // 8 warps -> k = 0..7
            float a1 = 0.f, a2 = 0.f;
#pragma unroll
            for (int u = 0; u < 32; u++) {
                a1 += e[u] * ipW1[k * 2048 +        u * 32 + lane];
                a2 += e[u] * ipW1[k * 2048 + 1024 + u * 32 + lane];
            }
            g_A12[t * 288 + k * 32 + lane] = make_float2(a1, a2);
        }
        if (wid == 0) {  // bias row
            float b1 = 0.f, b2 = 0.f;
#pragma unroll
            for (int u = 0; u < 32; u++) {
                b1 += e[u] * ipb1[       u * 32 + lane];
                b2 += e[u] * ipb1[1024 + u * 32 + lane];
            }
            g_A12[t * 288 + 8 * 32 + lane] = make_float2(b1, b2);
        }
        return;
    }
    int tid = (blockIdx.x - 100) * blockDim.x + threadIdx.x;
    int stride = (gridDim.x - 100) * blockDim.x;
    for (int i = tid; i < N * 32; i += stride) { g_s[i] = 0.f; g_cs[i] = 0.f; }
    for (int i = tid; i < N * 96; i += stride) { g_v[i] = 0.f; g_cv[i] = 0.f; }
    for (int i = tid; i < N;      i += stride) { g_cnt[i] = 0.f; g_deg_s[i] = 0; }
}

// ---------------- per-edge geometry + radial MLPs + stage-1 scatter + hist ----
__global__ void k_edge1(const float* __restrict__ coords,
                        const int*   __restrict__ atom_types,
                        const int*   __restrict__ ei,
                        const float* __restrict__ ipW0, const float* __restrict__ ipb0,
                        const float* __restrict__ lyW0, const float* __restrict__ lyb0,
                        const float* __restrict__ etW0, const float* __restrict__ etb0,
                        int E) {
    int lane = threadIdx.x & 31;
    int e = blockIdx.x * (blockDim.x >> 5) + (threadIdx.x >> 5);
    if (e >= E) return;
    int src = ei[e], dst = ei[E + e];

    float dx = coords[dst * 3 + 0] - coords[src * 3 + 0];
    float dy = coords[dst * 3 + 1] - coords[src * 3 + 1];
    float dz = coords[dst * 3 + 2] - coords[src * 3 + 2];
    float d  = sqrtf(dx * dx + dy * dy + dz * dz + 1e-12f);
    float inv_d = 1.f / d;
    float nx = dx * inv_d, ny = dy * inv_d, nz = dz * inv_d;
    float sh_0 = SQRT3 * ny, sh_1 = SQRT3 * nz, sh_2 = SQRT3 * nx;

    float attr[8];
    constexpr float STEP = CUTOFF / 9.0f;
    constexpr float INV_STEP = 9.0f / CUTOFF;
#pragma unroll
    for (int i = 0; i < 8; i++) {
        float diff = (d - (float)(i + 1) * STEP) * INV_STEP;
        attr[i] = __expf(-diff * diff) * (1.0f / 1.12f);
    }

    int grp = lane >> 3;
    int j   = lane & 7;
    const float* W0 = (grp == 1) ? lyW0 : (grp == 2) ? etW0 : ipW0;
    const float* b0 = (grp == 1) ? lyb0 : (grp == 2) ? etb0 : ipb0;
    float pre = b0[j];
#pragma unroll
    for (int i = 0; i < 8; i++) pre += attr[i] * W0[i * 8 + j];
    float myh = siluf(pre);

    if (grp == 1) g_hly[e * 8 + j] = myh;
    if (grp == 2) g_het[e * 8 + j] = myh;
    if (lane < 3) g_sh1[e * 3 + lane] = (lane == 0) ? sh_0 : (lane == 1) ? sh_1 : sh_2;

    int t = atom_types[src];
    const float2* A = &g_A12[t * 288];
    float2 bv = A[8 * 32 + lane];
    ull m = pack2(bv.x, bv.y);
#pragma unroll
    for (int k = 0; k < 8; k++) {
        float hk = __shfl_sync(FULLMASK, myh, k);
        float2 av = A[k * 32 + lane];
        m = fma2(pack2(av.x, av.y), pack2(hk, hk), m);
    }
    float m1, m2; unpack2(m, m1, m2);
    atomicAdd(&g_s[dst * 32 + lane], C_IP * m1);
    float cm2 = C_IP * m2;
    atomicAdd(&g_v[dst * 96 +      lane], cm2 * sh_0);
    atomicAdd(&g_v[dst * 96 + 32 + lane], cm2 * sh_1);
    atomicAdd(&g_v[dst * 96 + 64 + lane], cm2 * sh_2);
    if (lane == 0) {
        atomicAdd(&g_cnt[dst], 1.f);
        atomicAdd(&g_deg_s[src], 1);
    }
}

// ---------------- single-block scan (shfl two-level) --------------------------
__global__ void k_scan_s(int N) {
    __shared__ int wsum[32];
    int t = threadIdx.x;          // 1024 threads
    int lane = t & 31, wid = t >> 5;
    int base = t * 5;
    int c[5]; int tot = 0;
#pragma unroll
    for (int j = 0; j < 5; j++) {
        c[j] = (base + j < N) ? g_deg_s[base + j] : 0;
        tot += c[j];
    }
    int x = tot;
#pragma unroll
    for (int d = 1; d < 32; d <<= 1) {
        int y = __shfl_up_sync(FULLMASK, x, d);
        if (lane >= d) x += y;
    }
    if (lane == 31) wsum[wid] = x;
    __syncthreads();
    if (wid == 0) {
        int w = wsum[lane];
#pragma unroll
        for (int d = 1; d < 32; d <<= 1) {
            int y = __shfl_up_sync(FULLMASK, w, d);
            if (lane >= d) w += y;
        }
        wsum[lane] = w;
    }
    __syncthreads();
    int run = ((wid > 0) ? wsum[wid - 1] : 0) + x - tot;
#pragma unroll
    for (int j = 0; j < 5; j++) {
        if (base + j < N) { g_off_s[base + j] = run; g_cur_s[base + j] = run; run += c[j]; }
    }
    if (t == 0) g_off_s[N] = wsum[31];
}

// ---------------- fused: CSR fill + pre_ly (f32x2, 32 nodes/block, k-split) ---
// pre block bb: kseg = bb % 3 handles k in [kseg*3, kseg*3+3); nodes nb..nb+31.
// Each thread: lane w, warp q -> node pairs 2q, 2q+1 (nodes nb+4q..nb+4q+3).
// G[n][k][2 float4 rows][32 w]: {Y0,Y1,Z2_0,Z2_1} {Z2_2,Z3_0,Z3_1,Z3_2}
__global__ void __launch_bounds__(256)
k_fill_pre(const int* __restrict__ ei,
           const float* __restrict__ W1, const float* __restrict__ B1,
           int N, int E, int FILL_BLOCKS) {
    if ((int)blockIdx.x < FILL_BLOCKS) {
        int e = blockIdx.x * blockDim.x + threadIdx.x;
        if (e < E) {
            int p = atomicAdd(&g_cur_s[ei[e]], 1);
            g_csr_s[p] = e;
        }
        return;
    }
    __shared__ ull s_sm[32 * 16];       // [u][pair]
    __shared__ ull v_sm[3][32 * 16];
    __shared__ float inv_sm[32];
    int tid = threadIdx.x;
    int bb = blockIdx.x - FILL_BLOCKS;
    int kseg = bb % 3;             // k range [kseg*3, kseg*3+3)
    int nb = (bb / 3) * 32;        // 32 nodes per block

    if (tid < 32) {
        int n = nb + tid;
        inv_sm[tid] = (n < N) ? 1.f / fmaxf(g_cnt[n], 1.f) : 0.f;
    }
    __syncthreads();

    for (int idx = tid; idx < 32 * 16; idx += 256) {
        int j = idx & 15, u = idx >> 4;
        int n0 = nb + 2 * j, n1 = n0 + 1;
        float i0 = inv_sm[2 * j], i1 = inv_sm[2 * j + 1];
        float a0 = (n0 < N) ? g_s[n0 * 32 + u] * i0 : 0.f;
        float a1 = (n1 < N) ? g_s[n1 * 32 + u] * i1 : 0.f;
        s_sm[u * 16 + j] = pack2(a0, a1);
#pragma unroll
        for (int i = 0; i < 3; i++) {
            float b0 = (n0 < N) ? g_v[n0 * 96 + i * 32 + u] * i0 : 0.f;
            float b1 = (n1 < N) ? g_v[n1 * 96 + i * 32 + u] * i1 : 0.f;
            v_sm[i][u * 16 + j] = pack2(b0, b1);
        }
    }
    __syncthreads();

    int w = tid & 31;
    int q = tid >> 5;
    int p0 = 2 * q;                // pair indices p0, p0+1

#pragma unroll
    for (int kk = 0; kk < 3; kk++) {
        int k = kseg * 3 + kk;
        const float* Wk = (k < 8) ? (W1 + k * 4096) : B1;
        ull y0[2] = {0, 0}, y1[2] = {0, 0};
        ull z20[2] = {0, 0}, z21[2] = {0, 0}, z22[2] = {0, 0};
        ull z30[2] = {0, 0}, z31[2] = {0, 0}, z32[2] = {0, 0};
#pragma unroll 8
        for (int u = 0; u < 32; u++) {
            ull W0 = pack2(__ldg(&Wk[           u * 32 + w]), 0.f);
            ull Wa = pack2(__ldg(&Wk[1024 +     u * 32 + w]), 0.f);
            ull Wb = pack2(__ldg(&Wk[2048 +     u * 32 + w]), 0.f);
            ull Wc = pack2(__ldg(&Wk[3072 +     u * 32 + w]), 0.f);
            // duplicate low half into high half: w2 = (w,w)
            float t0, t1;
            unpack2(W0, t0, t1); W0 = pack2(t0, t0);
            unpack2(Wa, t0, t1); Wa = pack2(t0, t0);
            unpack2(Wb, t0, t1); Wb = pack2(t0, t0);
            unpack2(Wc, t0, t1); Wc = pack2(t0, t0);
#pragma unroll
            for (int pp = 0; pp < 2; pp++) {
                ull ss  = s_sm[u * 16 + p0 + pp];
                ull vv0 = v_sm[0][u * 16 + p0 + pp];
                ull vv1 = v_sm[1][u * 16 + p0 + pp];
                ull vv2 = v_sm[2][u * 16 + p0 + pp];
                y0[pp]  = fma2(ss,  W0, y0[pp]);
                y1[pp]  = fma2(ss,  Wa, y1[pp]);
                z20[pp] = fma2(vv0, Wb, z20[pp]);
                z21[pp] = fma2(vv1, Wb, z21[pp]);
                z22[pp] = fma2(vv2, Wb, z22[pp]);
                z30[pp] = fma2(vv0, Wc, z30[pp]);
                z31[pp] = fma2(vv1, Wc, z31[pp]);
                z32[pp] = fma2(vv2, Wc, z32[pp]);
            }
        }
#pragma unroll
        for (int pp = 0; pp < 2; pp++) {
            float y0l, y0h, y1l, y1h, a0l, a0h, a1l, a1h, a2l, a2h;
            float b0l, b0h, b1l, b1h, b2l, b2h;
            unpack2(y0[pp], y0l, y0h);   unpack2(y1[pp], y1l, y1h);
            unpack2(z20[pp], a0l, a0h);  unpack2(z21[pp], a1l, a1h);
            unpack2(z22[pp], a2l, a2h);
            unpack2(z30[pp], b0l, b0h);  unpack2(z31[pp], b1l, b1h);
            unpack2(z32[pp], b2l, b2h);
            int n = nb + 2 * (p0 + pp);
            if (n < N) {
                float4* Gp = reinterpret_cast<float4*>(&g_G[n * 2304]);
                Gp[(2 * k + 0) * 32 + w] = make_float4(y0l, y1l, a0l, a1l);
                Gp[(2 * k + 1) * 32 + w] = make_float4(a2l, b0l, b1l, b2l);
            }
            if (n + 1 < N) {
                float4* Gp = reinterpret_cast<float4*>(&g_G[(n + 1) * 2304]);
                Gp[(2 * k + 0) * 32 + w] = make_float4(y0h, y1h, a0h, a1h);
                Gp[(2 * k + 1) * 32 + w] = make_float4(a2h, b0h, b1h, b2h);
            }
        }
    }
}

// ---------------- apply ly: warp per src node, packed G, atomic scatter -------
__global__ void __launch_bounds__(128)
k_apply_ly(const int* __restrict__ ei, int N, int E) {
    int lane = threadIdx.x & 31;
    int n = blockIdx.x * 4 + (threadIdx.x >> 5);
    if (n >= N) return;
    int beg = g_off_s[n], end = g_off_s[n + 1];
    if (beg == end) return;

    const float4* Gp = reinterpret_cast<const float4*>(&g_G[n * 2304]);
    ull Gxy[9], Gzw[9], Hxy[9], Hzw[9];
#pragma unroll
    for (int k = 0; k < 9; k++) {
        float4 a = Gp[(2 * k + 0) * 32 + lane];
        float4 b = Gp[(2 * k + 1) * 32 + lane];
        Gxy[k] = pack2(a.x, a.y);  Gzw[k] = pack2(a.z, a.w);
        Hxy[k] = pack2(b.x, b.y);  Hzw[k] = pack2(b.z, b.w);
    }

    for (int p = beg; p < end; p++) {
        int e = g_csr_s[p];
        int dst = ei[E + e];
        float sh_0 = g_sh1[e * 3 + 0], sh_1 = g_sh1[e * 3 + 1], sh_2 = g_sh1[e * 3 + 2];
        const float4* hp = reinterpret_cast<const float4*>(&g_hly[e * 8]);
        float4 ha = hp[0], hb = hp[1];
        float h[9] = {ha.x, ha.y, ha.z, ha.w, hb.x, hb.y, hb.z, hb.w, 1.0f};

        ull acc1 = 0, acc2 = 0, acc3 = 0, acc4 = 0;
#pragma unroll
        for (int k = 0; k < 9; k++) {
            ull h2 = pack2(h[k], h[k]);
            acc1 = fma2(h2, Gxy[k], acc1);
            acc2 = fma2(h2, Gzw[k], acc2);
            acc3 = fma2(h2, Hxy[k], acc3);
            acc4 = fma2(h2, Hzw[k], acc4);
        }
        float ys, yv, z20, z21, z22, z30, z31, z32;
        unpack2(acc1, ys, yv);
        unpack2(acc2, z20, z21);
        unpack2(acc3, z22, z30);
        unpack2(acc4, z31, z32);

        float out_s = ys + INV_SQRT3 * (sh_0 * z30 + sh_1 * z31 + sh_2 * z32);
        atomicAdd(&g_cs[dst * 32 + lane],      C_LY * out_s);
        atomicAdd(&g_cv[dst * 96 +      lane], C_LY * (sh_0 * yv + z20));
        atomicAdd(&g_cv[dst * 96 + 32 + lane], C_LY * (sh_1 * yv + z21));
        atomicAdd(&g_cv[dst * 96 + 64 + lane], C_LY * (sh_2 * yv + z22));
    }
}

// ---------------- conv mean + linear self-interaction -------------------------
__global__ void k_norm2(const float* __restrict__ Ws, const float* __restrict__ Wv, int N) {
    int lane = threadIdx.x & 31;
    int n = blockIdx.x * (blockDim.x >> 5) + (threadIdx.x >> 5);
    if (n >= N) return;
    float inv = 1.f / fmaxf(g_cnt[n], 1.f);
    float sl  = g_s[n * 32 + lane]      * inv;
    float vl0 = g_v[n * 96 +      lane] * inv;
    float vl1 = g_v[n * 96 + 32 + lane] * inv;
    float vl2 = g_v[n * 96 + 64 + lane] * inv;
    float ls = 0.f, lv0 = 0.f, lv1 = 0.f, lv2 = 0.f;
#pragma unroll 4
    for (int u = 0; u < 32; u++) {
        float su  = __shfl_sync(FULLMASK, sl,  u);
        float vu0 = __shfl_sync(FULLMASK, vl0, u);
        float vu1 = __shfl_sync(FULLMASK, vl1, u);
        float vu2 = __shfl_sync(FULLMASK, vl2, u);
        float ws = Ws[u * 32 + lane];
        float wv = Wv[u * 32 + lane];
        ls  += su  * ws;
        lv0 += vu0 * wv;
        lv1 += vu1 * wv;
        lv2 += vu2 * wv;
    }
    g_s2[n * 32 + lane]      = g_cs[n * 32 + lane] * inv      + LC * ls;
    g_v2[n * 96 +      lane] = g_cv[n * 96 +      lane] * inv + LC * lv0;
    g_v2[n * 96 + 32 + lane] = g_cv[n * 96 + 32 + lane] * inv + LC * lv1;
    g_v2[n * 96 + 64 + lane] = g_cv[n * 96 + 64 + lane] * inv + LC * lv2;
}

// ---------------- fused output: et (grid-stride, blocks<ETB) + nodeout --------
__global__ void __launch_bounds__(256)
k_out(const float* __restrict__ W1, const float* __restrict__ B1,
      const int* __restrict__ ei,
      const float* __restrict__ noW1, const float* __restrict__ noW2,
      float* __restrict__ out, int N, int E, int ET_BLOCKS) {
    if ((int)blockIdx.x >= ET_BLOCKS) {
        int n = (blockIdx.x - ET_BLOCKS) * blockDim.x + threadIdx.x;
        if (n >= N) return;
        float s[32];
#pragma unroll
        for (int u = 0; u < 32; u++) s[u] = g_s2[n * 32 + u];
        float h[13];
#pragma unroll
        for (int j = 0; j < 13; j++) {
            float pre = 0.f;
#pragma unroll
            for (int u = 0; u < 32; u++) pre += s[u] * noW1[u * 13 + j];
            pre *= INV_SQRT32;
            h[j] = siluf(pre);
        }
        float* nout = out + (size_t)E * 5;
#pragma unroll
        for (int j2 = 0; j2 < 13; j2++) {
            float o = 0.f;
#pragma unroll
            for (int j = 0; j < 13; j++) o += h[j] * noW2[j * 13 + j2];
            nout[n * 13 + j2] = o * INV_SQRT13;
        }
        return;
    }
    __shared__ float sW[8 * 640];
    __shared__ float sB[640];
    for (int i = threadIdx.x; i < 8 * 640; i += blockDim.x) sW[i] = W1[i];
    for (int i = threadIdx.x; i < 640;     i += blockDim.x) sB[i] = B1[i];
    __syncthreads();

    int lane = threadIdx.x & 31;   // = u
    int gw = blockIdx.x * 8 + (threadIdx.x >> 5);
    int nwarps = ET_BLOCKS * 8;

    for (int e = gw; e < E; e += nwarps) {
        int src = ei[e], dst = ei[E + e];
        float sh_0 = g_sh1[e * 3 + 0], sh_1 = g_sh1[e * 3 + 1], sh_2 = g_sh1[e * 3 + 2];
        const float4* hp = reinterpret_cast<const float4*>(&g_het[e * 8]);
        float4 ha = hp[0], hb = hp[1];
        float h[8] = {ha.x, ha.y, ha.z, ha.w, hb.x, hb.y, hb.z, hb.w};

        float x[4];
        x[0] = g_s2[src * 32 + lane];
        {
            float a = g_v2[src * 96 +      lane];
            float b = g_v2[src * 96 + 32 + lane];
            float c = g_v2[src * 96 + 64 + lane];
            x[1] = (a * sh_0 + b * sh_1 + c * sh_2) * INV_SQRT3;
        }
        x[2] = g_s2[dst * 32 + lane];
        {
            float a = g_v2[dst * 96 +      lane];
            float b = g_v2[dst * 96 + 32 + lane];
            float c = g_v2[dst * 96 + 64 + lane];
            x[3] = (a * sh_0 + b * sh_1 + c * sh_2) * INV_SQRT3;
        }

        float p0 = 0.f, p1 = 0.f, p2 = 0.f, p3 = 0.f, p4 = 0.f;
#pragma unroll
        for (int P = 0; P < 4; P++) {
            int base = P * 160 + lane * 5;
            float xp = x[P];
#pragma unroll
            for (int w = 0; w < 5; w++) {
                float wt = sB[base + w];
#pragma unroll
                for (int k = 0; k < 8; k++) wt += h[k] * sW[k * 640 + base + w];
                float contrib = xp * wt;
                if (w == 0) p0 += contrib;
                else if (w == 1) p1 += contrib;
                else if (w == 2) p2 += contrib;
                else if (w == 3) p3 += contrib;
                else p4 += contrib;
            }
        }
#pragma unroll
        for (int off = 16; off > 0; off >>= 1) {
            p0 += __shfl_xor_sync(FULLMASK, p0, off);
            p1 += __shfl_xor_sync(FULLMASK, p1, off);
            p2 += __shfl_xor_sync(FULLMASK, p2, off);
            p3 += __shfl_xor_sync(FULLMASK, p3, off);
            p4 += __shfl_xor_sync(FULLMASK, p4, off);
        }
        if (lane == 0) {
            out[e * 5 + 0] = C_ET * p0;
            out[e * 5 + 1] = C_ET * p1;
            out[e * 5 + 2] = C_ET * p2;
            out[e * 5 + 3] = C_ET * p3;
            out[e * 5 + 4] = C_ET * p4;
        }
    }
}

// ---------------- launch ------------------------------------------------------

extern "C" void kernel_launch(void* const* d_in, const int* in_sizes, int n_in,
                              void* d_out, int out_size) {
    const float* coords     = (const float*)d_in[0];
    const int*   atom_types = (const int*)  d_in[1];
    const int*   ei         = (const int*)  d_in[2];
    const float* atom_embed = (const float*)d_in[3];
    const float* ip_W0 = (const float*)d_in[4];
    const float* ip_b0 = (const float*)d_in[5];
    const float* ip_W1 = (const float*)d_in[6];
    const float* ip_b1 = (const float*)d_in[7];
    const float* ly_W0 = (const float*)d_in[8];
    const float* ly_b0 = (const float*)d_in[9];
    const float* ly_W1 = (const float*)d_in[10];
    const float* ly_b1 = (const float*)d_in[11];
    const float* ly_Ws = (const float*)d_in[12];
    const float* ly_Wv = (const float*)d_in[13];
    const float* et_W0 = (const float*)d_in[14];
    const float* et_b0 = (const float*)d_in[15];
    const float* et_W1 = (const float*)d_in[16];
    const float* et_b1 = (const float*)d_in[17];
    const float* no_W1 = (const float*)d_in[18];
    const float* no_W2 = (const float*)d_in[19];
    float* out = (float*)d_out;

    int N = in_sizes[0] / 3;   // 5000
    int E = in_sizes[2] / 2;   // 40000

    const int FILL_BLOCKS = (E + 255) / 256;          // 157
    const int PRE_BLOCKS  = 3 * ((N + 31) / 32);      // 3 k-segments x 157
    const int ET_BLOCKS   = 296;
    const int NO_BLOCKS   = (N + 255) / 256;          // 20

    k_init<<<100 + 256, 256>>>(atom_embed, ip_W1, ip_b1, N);
    k_edge1<<<(E + 7) / 8, 256>>>(coords, atom_types, ei,
                                  ip_W0, ip_b0, ly_W0, ly_b0, et_W0, et_b0, E);
    k_scan_s<<<1, 1024>>>(N);
    k_fill_pre<<<FILL_BLOCKS + PRE_BLOCKS, 256>>>(ei, ly_W1, ly_b1, N, E, FILL_BLOCKS);
    k_apply_ly<<<(N + 3) / 4, 128>>>(ei, N, E);
    k_norm2<<<(N + 7) / 8, 256>>>(ly_Ws, ly_Wv, N);
    k_out<<<ET_BLOCKS + NO_BLOCKS, 256>>>(et_W1, et_b1, ei, no_W1, no_W2,
                                          out, N, E, ET_BLOCKS);
}